// round 10
// baseline (speedup 1.0000x reference)
#include <cuda_runtime.h>
#include <cuda_bf16.h>
#include <cstdint>
#include <cstddef>

typedef __nv_bfloat16 bf16;
typedef unsigned int u32;

#define NN 4096
#define DD 128
#define NB 2
#define RHO 5
#define NJ 5
#define KC 64
// Stage (32KB): A_hi[0,8K) A_lo[8K,16K) B_hi[16K,24K) B_lo[24K,32K)
#define STAGE_B 32768
#define SMEM_TOTAL (2 * STAGE_B)

// ---------------- device scratch ----------------
__device__ bf16 g_U_hi[(size_t)NB * NN * NN];
__device__ bf16 g_U_lo[(size_t)NB * NN * NN];
__device__ bf16 g_x_hi[(size_t)NB * NN * DD];
__device__ bf16 g_x_lo[(size_t)NB * NN * DD];
__device__ bf16 g_Z_hi[(size_t)NB * NN * DD];
__device__ bf16 g_Z_lo[(size_t)NB * NN * DD];
__device__ float g_p0[(size_t)NB * NN * DD];
__device__ float g_p1[(size_t)NB * NN * DD];
__device__ bf16 g_F_hi[(size_t)NB * NN * 6 * DD];
__device__ bf16 g_F_lo[(size_t)NB * NN * 6 * DD];
__device__ bf16 g_Wc_hi[6 * DD * DD];   // [768 k][128 d]
__device__ bf16 g_Wc_lo[6 * DD * DD];
__device__ float g_partial[NB * 32 * DD];
__device__ float g_acoef[NB * 8];
__device__ float g_bcoef[NB * 8];
__device__ float g_scale[NB * 8];
__device__ float g_cvec[DD];

// ---------------- helpers ----------------
__device__ __forceinline__ u32 smem_u32(const void* p) {
    u32 a;
    asm("{ .reg .u64 t; cvta.to.shared.u64 t, %1; cvt.u32.u64 %0, t; }" : "=r"(a) : "l"(p));
    return a;
}
__device__ __forceinline__ void split2(float v, bf16& h, bf16& l) {
    h = __float2bfloat16_rn(v);
    l = __float2bfloat16_rn(v - __bfloat162float(h));
}
__device__ __forceinline__ u32 packb(bf16 a, bf16 b) {
    return (u32)__bfloat16_as_ushort(a) | ((u32)__bfloat16_as_ushort(b) << 16);
}
__device__ __forceinline__ void ldsm4(u32 a, u32* r) {
    asm volatile("ldmatrix.sync.aligned.m8n8.x4.shared.b16 {%0,%1,%2,%3}, [%4];"
                 : "=r"(r[0]), "=r"(r[1]), "=r"(r[2]), "=r"(r[3]) : "r"(a));
}
__device__ __forceinline__ void ldsm4t(u32 a, u32* r) {
    asm volatile("ldmatrix.sync.aligned.m8n8.x4.trans.shared.b16 {%0,%1,%2,%3}, [%4];"
                 : "=r"(r[0]), "=r"(r[1]), "=r"(r[2]), "=r"(r[3]) : "r"(a));
}
__device__ __forceinline__ void mma16816(float* c, const u32* a, const u32* b) {
    asm volatile(
        "mma.sync.aligned.m16n8k16.row.col.f32.bf16.bf16.f32 "
        "{%0,%1,%2,%3}, {%4,%5,%6,%7}, {%8,%9}, {%0,%1,%2,%3};"
        : "+f"(c[0]), "+f"(c[1]), "+f"(c[2]), "+f"(c[3])
        : "r"(a[0]), "r"(a[1]), "r"(a[2]), "r"(a[3]), "r"(b[0]), "r"(b[1]));
}

// ---------------- standalone small kernels ----------------
__global__ void convert_split_kernel(const float* __restrict__ src, bf16* __restrict__ oh,
                                     bf16* __restrict__ ol) {
    size_t idx = (size_t)blockIdx.x * blockDim.x + threadIdx.x;
    float4 v = ((const float4*)src)[idx];
    bf16 h0, l0, h1, l1, h2, l2, h3, l3;
    split2(v.x, h0, l0); split2(v.y, h1, l1);
    split2(v.z, h2, l2); split2(v.w, h3, l3);
    ((u32*)oh)[idx * 2] = packb(h0, h1);
    ((u32*)oh)[idx * 2 + 1] = packb(h2, h3);
    ((u32*)ol)[idx * 2] = packb(l0, l1);
    ((u32*)ol)[idx * 2 + 1] = packb(l2, l3);
}

__global__ void combine_bias_kernel(const float* __restrict__ p0, const float* __restrict__ p1,
                                    const float* __restrict__ bias, float* __restrict__ dst) {
    size_t i = (size_t)blockIdx.x * blockDim.x + threadIdx.x;
    int col = ((int)(i & 31)) * 4;
    float4 a = ((const float4*)p0)[i], b = ((const float4*)p1)[i];
    ((float4*)dst)[i] = make_float4(a.x + b.x + bias[col], a.y + b.y + bias[col + 1],
                                    a.z + b.z + bias[col + 2], a.w + b.w + bias[col + 3]);
}

__global__ void partial_kernel(const float* __restrict__ eigvs) {
    int b = blockIdx.x >> 5, chunk = blockIdx.x & 31, d = threadIdx.x;
    const float* p = eigvs + ((size_t)b * NN + (size_t)chunk * 128) * DD + d;
    float s = 0.f;
#pragma unroll 8
    for (int r = 0; r < 128; r++) s += p[(size_t)r * DD];
    g_partial[(b * 32 + chunk) * DD + d] = s;
}

__global__ void coeff_kernel(const float* __restrict__ Wa, const float* __restrict__ ba,
                             const float* __restrict__ Wb, const float* __restrict__ bb,
                             const float* __restrict__ Ws, const float* __restrict__ bs) {
    __shared__ float mean[DD];
    int b = blockIdx.x, d = threadIdx.x;
    float s = 0.f;
    for (int c = 0; c < 32; c++) s += g_partial[(b * 32 + c) * DD + d];
    mean[d] = s * (1.0f / NN);
    __syncthreads();
    if (d < RHO) {
        float a = 0.f, bv = 0.f, sv = 0.f;
        for (int e = 0; e < DD; e++) {
            float m = mean[e];
            a += m * Wa[e * RHO + d];
            bv += m * Wb[e * RHO + d];
            sv += m * Ws[e * NJ + d];
        }
        g_acoef[b * 8 + d] = a + ba[d];
        g_bcoef[b * 8 + d] = bv + bb[d];
        sv += bs[d];
        g_scale[b * 8 + d] = 5.0f / (1.0f + expf(-sv));
    }
}

__global__ void weight_kernel(const float* __restrict__ WS_, const float* __restrict__ WM,
                              const float* __restrict__ Ww, const float* __restrict__ bS,
                              const float* __restrict__ bM, const float* __restrict__ bw) {
    int blk = blockIdx.x, d = threadIdx.x;
    if (blk < 6 * DD) {
        int s = blk >> 7, i = blk & 127;
        const float* wsrc = (s == 0) ? (WS_ + i * DD) : (WM + (size_t)(s - 1) * DD * DD + i * DD);
        float acc = 0.f;
        for (int e = 0; e < DD; e++) acc += wsrc[e] * Ww[e * DD + d];
        bf16 h, l; split2(acc, h, l);
        g_Wc_hi[(size_t)blk * DD + d] = h;
        g_Wc_lo[(size_t)blk * DD + d] = l;
    } else {
        float acc = bw[d];
        for (int e = 0; e < DD; e++) {
            float cb = bS[e];
            for (int j = 0; j < NJ; j++) cb += bM[j * DD + e];
            acc += cb * Ww[e * DD + d];
        }
        g_cvec[d] = acc;
    }
}

// ---------------- role device functions ----------------
__device__ void conv_role(const float* __restrict__ src, bf16* __restrict__ oh,
                          bf16* __restrict__ ol, int cta, int ncta, int n4) {
    for (int i = cta * 128 + threadIdx.x; i < n4; i += ncta * 128) {
        float4 v = ((const float4*)src)[i];
        bf16 h0, l0, h1, l1, h2, l2, h3, l3;
        split2(v.x, h0, l0); split2(v.y, h1, l1);
        split2(v.z, h2, l2); split2(v.w, h3, l3);
        ((u32*)oh)[(size_t)i * 2] = packb(h0, h1);
        ((u32*)oh)[(size_t)i * 2 + 1] = packb(h2, h3);
        ((u32*)ol)[(size_t)i * 2] = packb(l0, l1);
        ((u32*)ol)[(size_t)i * 2 + 1] = packb(l2, l3);
    }
}

// fbuild for one batch: 128 role CTAs x 32 rows
__device__ void fbuild_role(const float* __restrict__ eigvs, int b, int cta) {
    int d = threadIdx.x;
    int row0 = b * NN + cta * 32;
    for (int r = 0; r < 32; r++) {
        int row = row0 + r;
        const float* ac = g_acoef + b * 8;
        const float* bc = g_bcoef + b * 8;
        const float* sc = g_scale + b * 8;
        size_t idx = (size_t)row * DD + d;
        float e = eigvs[idx];
        float xv = g_p0[idx] + g_p1[idx];
        float To = 1.f, Te = e, h = bc[0];
#pragma unroll
        for (int i = 1; i < RHO; i++) {
            To = 2.f * e * Te - To;
            Te = 2.f * e * To - Te;
            h += bc[i] * To;
        }
        size_t fb = (size_t)row * (6 * DD);
        bf16 hh, hl; split2(h * xv, hh, hl);
        g_F_hi[fb + d] = hh; g_F_lo[fb + d] = hl;
#pragma unroll
        for (int j = 0; j < NJ; j++) {
            float sx = sc[j] * e;
            float To2 = 1.f, Te2 = sx, g = ac[0] * Te2;
#pragma unroll
            for (int i = 1; i < RHO; i++) {
                To2 = 2.f * sx * Te2 - To2;
                Te2 = 2.f * sx * To2 - Te2;
                g += ac[i] * Te2;
            }
            bf16 gh, gl; split2(g * xv, gh, gl);
            g_F_hi[fb + (1 + j) * DD + d] = gh;
            g_F_lo[fb + (1 + j) * DD + d] = gl;
        }
    }
}

__device__ void combine_role(const float* __restrict__ p0, const float* __restrict__ p1,
                             const float* __restrict__ bias, float* __restrict__ dst,
                             int cta, int ncta, int n4) {
    for (int i = cta * 128 + threadIdx.x; i < n4; i += ncta * 128) {
        int col = (i & 31) * 4;
        float4 a = ((const float4*)p0)[i], b = ((const float4*)p1)[i];
        ((float4*)dst)[i] = make_float4(a.x + b.x + bias[col], a.y + b.y + bias[col + 1],
                                        a.z + b.z + bias[col + 2], a.w + b.w + bias[col + 3]);
    }
}

// ---------------- gemm device function: BM=64 x BN=64, 128 threads, 2 stages ----------------
template <bool TRANSA>
__device__ __forceinline__ void loadA_async(u32 Abase, int k0, const bf16* Ah, const bf16* Al,
                                            int lda, int tid) {
#pragma unroll
    for (int half = 0; half < 2; half++) {
        const bf16* src = half ? Al : Ah;
        u32 ab = Abase + half * 8192;
#pragma unroll
        for (int i = 0; i < 4; i++) {
            int q = tid + i * 128;
            int row = q >> 3, ch = q & 7;
            const char* g;
            if (TRANSA) g = (const char*)(src + (size_t)(k0 + row) * lda) + ch * 16;
            else        g = (const char*)(src + (size_t)row * lda + k0) + ch * 16;
            u32 dst = ab + row * 128 + ((ch ^ (row & 7)) * 16);
            asm volatile("cp.async.cg.shared.global [%0], [%1], 16;" :: "r"(dst), "l"(g));
        }
    }
}

__device__ __forceinline__ void loadB_async(u32 Bbase, int k0, const bf16* Bh, const bf16* Bl,
                                            int ldb, int tid) {
#pragma unroll
    for (int half = 0; half < 2; half++) {
        const bf16* src = half ? Bl : Bh;
        u32 bb = Bbase + half * 8192;
#pragma unroll
        for (int i = 0; i < 4; i++) {
            int q = tid + i * 128;
            int kr = q >> 3, ch = q & 7;
            const char* g = (const char*)(src + (size_t)(k0 + kr) * ldb) + ch * 16;
            u32 dst = bb + kr * 128 + ((ch ^ (kr & 7)) * 16);
            asm volatile("cp.async.cg.shared.global [%0], [%1], 16;" :: "r"(dst), "l"(g));
        }
    }
}

// OUTMODE: 0 = fp32 partial (C0/C1 by ks), 2 = bf16 hi/lo split output
template <bool TRANSA, int OUTMODE>
__device__ void gemm_dev(const bf16* __restrict__ Ah, const bf16* __restrict__ Al,
                         const bf16* __restrict__ Bh, const bf16* __restrict__ Bl,
                         float* __restrict__ C0, float* __restrict__ C1,
                         bf16* __restrict__ Zh, bf16* __restrict__ Zl,
                         int nsplit, int K, int lda, int ldb,
                         int bx, int nh, int ks) {
    extern __shared__ char smem[];
    u32 sb = smem_u32(smem);
    int tid = threadIdx.x, lane = tid & 31, wid = tid >> 5;
    int wm = wid & 1, wn = wid >> 1;
    const int Klocal = K / nsplit;
    const int kofs = ks * Klocal;

    if (TRANSA) { Ah += (size_t)kofs * lda + (size_t)bx * 64; Al += (size_t)kofs * lda + (size_t)bx * 64; }
    else        { Ah += (size_t)bx * 64 * lda + kofs;         Al += (size_t)bx * 64 * lda + kofs; }
    Bh += (size_t)kofs * ldb + (size_t)nh * 64;
    Bl += (size_t)kofs * ldb + (size_t)nh * 64;

    float acc[2][4][4];
#pragma unroll
    for (int a = 0; a < 2; a++)
#pragma unroll
        for (int b = 0; b < 4; b++)
#pragma unroll
            for (int c = 0; c < 4; c++) acc[a][b][c] = 0.f;

    const int NCH = Klocal / KC;

#pragma unroll
    for (int s = 0; s < 2; s++) {
        u32 Abase = sb + s * STAGE_B;
        loadA_async<TRANSA>(Abase, s * KC, Ah, Al, lda, tid);
        loadB_async(Abase + 16384, s * KC, Bh, Bl, ldb, tid);
        asm volatile("cp.async.commit_group;" ::: "memory");
    }

    for (int c = 0; c < NCH; c++) {
        int st = c & 1;
        if (c + 1 < NCH) asm volatile("cp.async.wait_group 1;" ::: "memory");
        else             asm volatile("cp.async.wait_group 0;" ::: "memory");
        __syncthreads();

        u32 Ab = sb + st * STAGE_B;
        u32 Bb = Ab + 16384;
#pragma unroll
        for (int s = 0; s < 4; s++) {
            u32 ah[2][4], al[2][4], bh[2][4], bl[2][4];
#pragma unroll
            for (int mt = 0; mt < 2; mt++) {
                u32 off;
                if (TRANSA) {
                    int kr = 16 * s + (lane & 7) + ((lane >> 4) << 3);
                    int mch = wm * 4 + mt * 2 + ((lane >> 3) & 1);
                    off = kr * 128 + ((mch ^ (kr & 7)) << 4);
                    ldsm4t(Ab + off, ah[mt]);
                    ldsm4t(Ab + 8192 + off, al[mt]);
                } else {
                    int row = wm * 32 + mt * 16 + (lane & 15);
                    int ch = 2 * s + (lane >> 4);
                    off = row * 128 + ((ch ^ (row & 7)) << 4);
                    ldsm4(Ab + off, ah[mt]);
                    ldsm4(Ab + 8192 + off, al[mt]);
                }
            }
#pragma unroll
            for (int nt = 0; nt < 2; nt++) {
                int kr = 16 * s + (lane & 7) + ((lane >> 3) & 1) * 8;
                int nch = wn * 4 + nt * 2 + (lane >> 4);
                u32 off = kr * 128 + ((nch ^ (kr & 7)) << 4);
                ldsm4t(Bb + off, bh[nt]);
                ldsm4t(Bb + 8192 + off, bl[nt]);
            }
#pragma unroll
            for (int mt = 0; mt < 2; mt++)
#pragma unroll
                for (int nt = 0; nt < 2; nt++)
#pragma unroll
                    for (int oc = 0; oc < 2; oc++) {
                        float* cc = acc[mt][nt * 2 + oc];
                        mma16816(cc, ah[mt], &bh[nt][oc * 2]);
                        mma16816(cc, ah[mt], &bl[nt][oc * 2]);
                        mma16816(cc, al[mt], &bh[nt][oc * 2]);
                    }
        }
        __syncthreads();
        if (c + 2 < NCH) {
            u32 Abase = sb + st * STAGE_B;
            loadA_async<TRANSA>(Abase, (c + 2) * KC, Ah, Al, lda, tid);
            loadB_async(Abase + 16384, (c + 2) * KC, Bh, Bl, ldb, tid);
            asm volatile("cp.async.commit_group;" ::: "memory");
        }
    }

    float* C = (ks == 0) ? C0 : C1;
#pragma unroll
    for (int mt = 0; mt < 2; mt++)
#pragma unroll
        for (int j = 0; j < 4; j++) {
            int mloc = bx * 64 + wm * 32 + mt * 16 + (lane >> 2);
            int col = nh * 64 + wn * 32 + j * 8 + (lane & 3) * 2;
#pragma unroll
            for (int rr = 0; rr < 2; rr++) {
                float v0 = acc[mt][j][rr * 2], v1 = acc[mt][j][rr * 2 + 1];
                size_t off = (size_t)(mloc + rr * 8) * 128 + col;
                if (OUTMODE == 2) {
                    bf16 h0, l0, h1, l1;
                    split2(v0, h0, l0); split2(v1, h1, l1);
                    *(u32*)(Zh + off) = packb(h0, h1);
                    *(u32*)(Zl + off) = packb(l0, l1);
                } else {
                    *(float2*)(C + off) = make_float2(v0, v1);
                }
            }
        }
}

// ---------------- fused heterogeneous kernels ----------------
// K2: gemm1(b0) [z<2] + convert U(b1) [z==2]
__global__ void __launch_bounds__(128, 3)
k2_gemm1b0_convb1(const bf16* Ah, const bf16* Al, const bf16* Bh, const bf16* Bl,
                  float* C0, float* C1,
                  const float* Usrc, bf16* Uh, bf16* Ul) {
    if (blockIdx.z < 2)
        gemm_dev<true, 0>(Ah, Al, Bh, Bl, C0, C1, nullptr, nullptr,
                          2, NN, NN, DD, blockIdx.x, blockIdx.y, blockIdx.z);
    else
        conv_role(Usrc, Uh, Ul, blockIdx.x + 64 * blockIdx.y, 128, NN * NN / 4);
}

// K3: gemm1(b1) [z<2] + fbuild(b0) [z==2]
__global__ void __launch_bounds__(128, 3)
k3_gemm1b1_fbb0(const bf16* Ah, const bf16* Al, const bf16* Bh, const bf16* Bl,
                float* C0, float* C1, const float* eigvs) {
    if (blockIdx.z < 2)
        gemm_dev<true, 0>(Ah, Al, Bh, Bl, C0, C1, nullptr, nullptr,
                          2, NN, NN, DD, blockIdx.x, blockIdx.y, blockIdx.z);
    else
        fbuild_role(eigvs, 0, blockIdx.x + 64 * blockIdx.y);
}

// K4: gemm2(b0) [z==0] + fbuild(b1) [z==1]
__global__ void __launch_bounds__(128, 3)
k4_gemm2b0_fbb1(const bf16* Fh, const bf16* Fl, const bf16* Wh, const bf16* Wl,
                bf16* Zh, bf16* Zl, const float* eigvs) {
    if (blockIdx.z == 0)
        gemm_dev<false, 2>(Fh, Fl, Wh, Wl, nullptr, nullptr, Zh, Zl,
                           1, 6 * DD, 6 * DD, DD, blockIdx.x, blockIdx.y, 0);
    else
        fbuild_role(eigvs, 1, blockIdx.x + 64 * blockIdx.y);
}

// K5: gemm3(b0) [z<2] + gemm2(b1) [z==2]
__global__ void __launch_bounds__(128, 3)
k5_gemm3b0_gemm2b1(const bf16* Ah, const bf16* Al, const bf16* Bh, const bf16* Bl,
                   float* C0, float* C1,
                   const bf16* Fh, const bf16* Fl, const bf16* Wh, const bf16* Wl,
                   bf16* Zh, bf16* Zl) {
    if (blockIdx.z < 2)
        gemm_dev<false, 0>(Ah, Al, Bh, Bl, C0, C1, nullptr, nullptr,
                           2, NN, NN, DD, blockIdx.x, blockIdx.y, blockIdx.z);
    else
        gemm_dev<false, 2>(Fh, Fl, Wh, Wl, nullptr, nullptr, Zh, Zl,
                           1, 6 * DD, 6 * DD, DD, blockIdx.x, blockIdx.y, 0);
}

// K6: gemm3(b1) [z<2] + combine(b0) [z==2]
__global__ void __launch_bounds__(128, 3)
k6_gemm3b1_cbb0(const bf16* Ah, const bf16* Al, const bf16* Bh, const bf16* Bl,
                float* C0, float* C1,
                const float* p0, const float* p1, const float* bias, float* dst) {
    if (blockIdx.z < 2)
        gemm_dev<false, 0>(Ah, Al, Bh, Bl, C0, C1, nullptr, nullptr,
                           2, NN, NN, DD, blockIdx.x, blockIdx.y, blockIdx.z);
    else
        combine_role(p0, p1, bias, dst, blockIdx.x + 64 * blockIdx.y, 128, NN * DD / 4);
}

// ---------------------------------------------------------------
extern "C" void kernel_launch(void* const* d_in, const int* in_sizes, int n_in,
                              void* d_out, int out_size) {
    const float* eigvs = (const float*)d_in[0];
    const float* x = (const float*)d_in[1];
    const float* U = (const float*)d_in[2];
    const float* Wa = (const float*)d_in[3];
    const float* ba = (const float*)d_in[4];
    const float* Wb = (const float*)d_in[5];
    const float* bb = (const float*)d_in[6];
    const float* Ws = (const float*)d_in[7];
    const float* bs = (const float*)d_in[8];
    const float* WS_ = (const float*)d_in[9];
    const float* bS = (const float*)d_in[10];
    const float* WM = (const float*)d_in[11];
    const float* bM = (const float*)d_in[12];
    const float* Ww = (const float*)d_in[13];
    const float* bw = (const float*)d_in[14];
    float* out = (float*)d_out;

    cudaFuncSetAttribute(k2_gemm1b0_convb1, cudaFuncAttributeMaxDynamicSharedMemorySize, SMEM_TOTAL);
    cudaFuncSetAttribute(k3_gemm1b1_fbb0, cudaFuncAttributeMaxDynamicSharedMemorySize, SMEM_TOTAL);
    cudaFuncSetAttribute(k4_gemm2b0_fbb1, cudaFuncAttributeMaxDynamicSharedMemorySize, SMEM_TOTAL);
    cudaFuncSetAttribute(k5_gemm3b0_gemm2b1, cudaFuncAttributeMaxDynamicSharedMemorySize, SMEM_TOTAL);
    cudaFuncSetAttribute(k6_gemm3b1_cbb0, cudaFuncAttributeMaxDynamicSharedMemorySize, SMEM_TOTAL);

    bf16 *pUh, *pUl, *pxh, *pxl, *pZh, *pZl, *pFh, *pFl, *pWh, *pWl;
    float *pcv, *pp0, *pp1;
    cudaGetSymbolAddress((void**)&pUh, g_U_hi);
    cudaGetSymbolAddress((void**)&pUl, g_U_lo);
    cudaGetSymbolAddress((void**)&pxh, g_x_hi);
    cudaGetSymbolAddress((void**)&pxl, g_x_lo);
    cudaGetSymbolAddress((void**)&pZh, g_Z_hi);
    cudaGetSymbolAddress((void**)&pZl, g_Z_lo);
    cudaGetSymbolAddress((void**)&pFh, g_F_hi);
    cudaGetSymbolAddress((void**)&pFl, g_F_lo);
    cudaGetSymbolAddress((void**)&pWh, g_Wc_hi);
    cudaGetSymbolAddress((void**)&pWl, g_Wc_lo);
    cudaGetSymbolAddress((void**)&pcv, g_cvec);
    cudaGetSymbolAddress((void**)&pp0, g_p0);
    cudaGetSymbolAddress((void**)&pp1, g_p1);

    const size_t sU = (size_t)NN * NN;
    const size_t sX = (size_t)NN * DD;
    const size_t sF = (size_t)NN * 6 * DD;

    // K1 stage: convert U(b0) + x(both) + coefficient path
    convert_split_kernel<<<16384, 256>>>(U, pUh, pUl);                 // batch 0 only
    convert_split_kernel<<<1024, 256>>>(x, pxh, pxl);                  // both batches
    partial_kernel<<<64, 128>>>(eigvs);
    coeff_kernel<<<2, 128>>>(Wa, ba, Wb, bb, Ws, bs);
    weight_kernel<<<769, 128>>>(WS_, WM, Ww, bS, bM, bw);

    // K2: gemm1(b0) + convert U(b1)
    k2_gemm1b0_convb1<<<dim3(64, 2, 3), 128, SMEM_TOTAL>>>(
        pUh, pUl, pxh, pxl, pp0, pp1,
        U + sU, pUh + sU, pUl + sU);

    // K3: gemm1(b1) + fbuild(b0)
    k3_gemm1b1_fbb0<<<dim3(64, 2, 3), 128, SMEM_TOTAL>>>(
        pUh + sU, pUl + sU, pxh + sX, pxl + sX, pp0 + sX, pp1 + sX, eigvs);

    // K4: gemm2(b0) + fbuild(b1)
    k4_gemm2b0_fbb1<<<dim3(64, 2, 2), 128, SMEM_TOTAL>>>(
        pFh, pFl, pWh, pWl, pZh, pZl, eigvs);

    // K5: gemm3(b0) + gemm2(b1)
    k5_gemm3b0_gemm2b1<<<dim3(64, 2, 3), 128, SMEM_TOTAL>>>(
        pUh, pUl, pZh, pZl, pp0, pp1,
        pFh + sF, pFl + sF, pWh, pWl, pZh + sX, pZl + sX);

    // K6: gemm3(b1) + combine(b0)
    k6_gemm3b1_cbb0<<<dim3(64, 2, 3), 128, SMEM_TOTAL>>>(
        pUh + sU, pUl + sU, pZh + sX, pZl + sX, pp0 + sX, pp1 + sX,
        pp0, pp1, pcv, out);

    // K7: combine(b1)
    combine_bias_kernel<<<512, 256>>>(pp0 + sX, pp1 + sX, pcv, out + sX);
}

// round 11
// speedup vs baseline: 1.1098x; 1.1098x over previous
#include <cuda_runtime.h>
#include <cuda_bf16.h>
#include <cstdint>
#include <cstddef>

typedef __nv_bfloat16 bf16;
typedef unsigned int u32;

#define NN 4096
#define DD 128
#define NB 2
#define RHO 5
#define NJ 5
#define KC 64
// Stage (48KB): A_hi[0,16K) A_lo[16K,32K) B_hi[32K,40K) B_lo[40K,48K)
#define STAGE_B 49152
#define SMEM_TOTAL (2 * STAGE_B)

// ---------------- device scratch ----------------
__device__ bf16 g_U_hi[(size_t)NB * NN * NN];
__device__ bf16 g_U_lo[(size_t)NB * NN * NN];
__device__ bf16 g_x_hi[(size_t)NB * NN * DD];
__device__ bf16 g_x_lo[(size_t)NB * NN * DD];
__device__ bf16 g_Z_hi[(size_t)NB * NN * DD];
__device__ bf16 g_Z_lo[(size_t)NB * NN * DD];
__device__ float g_p0[(size_t)NB * NN * DD];
__device__ float g_p1[(size_t)NB * NN * DD];
__device__ bf16 g_F_hi[(size_t)NB * NN * 6 * DD];
__device__ bf16 g_F_lo[(size_t)NB * NN * 6 * DD];
__device__ bf16 g_Wc_hi[6 * DD * DD];   // [768 k][128 d]
__device__ bf16 g_Wc_lo[6 * DD * DD];
__device__ float g_partial[NB * 32 * DD];
__device__ float g_acoef[NB * 8];
__device__ float g_bcoef[NB * 8];
__device__ float g_scale[NB * 8];
__device__ float g_cvec[DD];

// ---------------- helpers ----------------
__device__ __forceinline__ u32 smem_u32(const void* p) {
    u32 a;
    asm("{ .reg .u64 t; cvta.to.shared.u64 t, %1; cvt.u32.u64 %0, t; }" : "=r"(a) : "l"(p));
    return a;
}
__device__ __forceinline__ void split2(float v, bf16& h, bf16& l) {
    h = __float2bfloat16_rn(v);
    l = __float2bfloat16_rn(v - __bfloat162float(h));
}
__device__ __forceinline__ u32 packb(bf16 a, bf16 b) {
    return (u32)__bfloat16_as_ushort(a) | ((u32)__bfloat16_as_ushort(b) << 16);
}
__device__ __forceinline__ void ldsm4(u32 a, u32* r) {
    asm volatile("ldmatrix.sync.aligned.m8n8.x4.shared.b16 {%0,%1,%2,%3}, [%4];"
                 : "=r"(r[0]), "=r"(r[1]), "=r"(r[2]), "=r"(r[3]) : "r"(a));
}
__device__ __forceinline__ void ldsm4t(u32 a, u32* r) {
    asm volatile("ldmatrix.sync.aligned.m8n8.x4.trans.shared.b16 {%0,%1,%2,%3}, [%4];"
                 : "=r"(r[0]), "=r"(r[1]), "=r"(r[2]), "=r"(r[3]) : "r"(a));
}
__device__ __forceinline__ void mma16816(float* c, const u32* a, const u32* b) {
    asm volatile(
        "mma.sync.aligned.m16n8k16.row.col.f32.bf16.bf16.f32 "
        "{%0,%1,%2,%3}, {%4,%5,%6,%7}, {%8,%9}, {%0,%1,%2,%3};"
        : "+f"(c[0]), "+f"(c[1]), "+f"(c[2]), "+f"(c[3])
        : "r"(a[0]), "r"(a[1]), "r"(a[2]), "r"(a[3]), "r"(b[0]), "r"(b[1]));
}

// ---------------- elementwise fp32 -> bf16 hi/lo ----------------
__global__ void convert_split_kernel(const float* __restrict__ src, bf16* __restrict__ oh,
                                     bf16* __restrict__ ol) {
    size_t idx = (size_t)blockIdx.x * blockDim.x + threadIdx.x;
    float4 v = ((const float4*)src)[idx];
    bf16 h0, l0, h1, l1, h2, l2, h3, l3;
    split2(v.x, h0, l0); split2(v.y, h1, l1);
    split2(v.z, h2, l2); split2(v.w, h3, l3);
    ((u32*)oh)[idx * 2] = packb(h0, h1);
    ((u32*)oh)[idx * 2 + 1] = packb(h2, h3);
    ((u32*)ol)[idx * 2] = packb(l0, l1);
    ((u32*)ol)[idx * 2 + 1] = packb(l2, l3);
}

// ---------------- split-K bias combine (deterministic) ----------------
__global__ void combine_bias_kernel(const float* __restrict__ p0, const float* __restrict__ p1,
                                    const float* __restrict__ bias, float* __restrict__ dst) {
    size_t i = (size_t)blockIdx.x * blockDim.x + threadIdx.x;
    int col = ((int)(i & 31)) * 4;
    float4 a = ((const float4*)p0)[i], b = ((const float4*)p1)[i];
    ((float4*)dst)[i] = make_float4(a.x + b.x + bias[col], a.y + b.y + bias[col + 1],
                                    a.z + b.z + bias[col + 2], a.w + b.w + bias[col + 3]);
}

// ---------------- coefficient path ----------------
__global__ void partial_kernel(const float* __restrict__ eigvs) {
    int b = blockIdx.x >> 5, chunk = blockIdx.x & 31, d = threadIdx.x;
    const float* p = eigvs + ((size_t)b * NN + (size_t)chunk * 128) * DD + d;
    float s = 0.f;
#pragma unroll 8
    for (int r = 0; r < 128; r++) s += p[(size_t)r * DD];
    g_partial[(b * 32 + chunk) * DD + d] = s;
}

// Parallelized: 128 threads compute all products, tree-reduce in smem.
__global__ void coeff_kernel(const float* __restrict__ Wa, const float* __restrict__ ba,
                             const float* __restrict__ Wb, const float* __restrict__ bb,
                             const float* __restrict__ Ws, const float* __restrict__ bs) {
    __shared__ float red[15][128];
    int b = blockIdx.x, d = threadIdx.x;
    float s = 0.f;
    for (int c = 0; c < 32; c++) s += g_partial[(b * 32 + c) * DD + d];
    float m = s * (1.0f / NN);
#pragma unroll
    for (int j = 0; j < RHO; j++) {
        red[j][d] = m * Wa[d * RHO + j];
        red[5 + j][d] = m * Wb[d * RHO + j];
        red[10 + j][d] = m * Ws[d * NJ + j];
    }
    __syncthreads();
#pragma unroll
    for (int off = 64; off >= 1; off >>= 1) {
        for (int idx = d; idx < 15 * off; idx += 128) {
            int k = idx / off, e = idx - k * off;
            red[k][e] += red[k][e + off];
        }
        __syncthreads();
    }
    if (d < RHO) {
        g_acoef[b * 8 + d] = red[d][0] + ba[d];
        g_bcoef[b * 8 + d] = red[5 + d][0] + bb[d];
        float sv = red[10 + d][0] + bs[d];
        g_scale[b * 8 + d] = 5.0f / (1.0f + expf(-sv));
    }
}

__global__ void weight_kernel(const float* __restrict__ WS_, const float* __restrict__ WM,
                              const float* __restrict__ Ww, const float* __restrict__ bS,
                              const float* __restrict__ bM, const float* __restrict__ bw) {
    int blk = blockIdx.x, d = threadIdx.x;
    if (blk < 6 * DD) {
        int s = blk >> 7, i = blk & 127;
        const float* wsrc = (s == 0) ? (WS_ + i * DD) : (WM + (size_t)(s - 1) * DD * DD + i * DD);
        float acc = 0.f;
        for (int e = 0; e < DD; e++) acc += wsrc[e] * Ww[e * DD + d];
        bf16 h, l; split2(acc, h, l);
        g_Wc_hi[(size_t)blk * DD + d] = h;
        g_Wc_lo[(size_t)blk * DD + d] = l;
    } else {
        float acc = bw[d];
        for (int e = 0; e < DD; e++) {
            float cb = bS[e];
            for (int j = 0; j < NJ; j++) cb += bM[j * DD + e];
            acc += cb * Ww[e * DD + d];
        }
        g_cvec[d] = acc;
    }
}

// fbuild reads split-K partials directly (xt = p0 + p1)
__global__ void fbuild_kernel(const float* __restrict__ eigvs) {
    int row0 = blockIdx.x * 16, d = threadIdx.x;
    for (int r = 0; r < 16; r++) {
        int row = row0 + r, b = row >> 12;
        const float* ac = g_acoef + b * 8;
        const float* bc = g_bcoef + b * 8;
        const float* sc = g_scale + b * 8;
        size_t idx = (size_t)row * DD + d;
        float e = eigvs[idx];
        float xv = g_p0[idx] + g_p1[idx];
        float To = 1.f, Te = e, h = bc[0];
#pragma unroll
        for (int i = 1; i < RHO; i++) {
            To = 2.f * e * Te - To;
            Te = 2.f * e * To - Te;
            h += bc[i] * To;
        }
        size_t fb = (size_t)row * (6 * DD);
        bf16 hh, hl; split2(h * xv, hh, hl);
        g_F_hi[fb + d] = hh; g_F_lo[fb + d] = hl;
#pragma unroll
        for (int j = 0; j < NJ; j++) {
            float sx = sc[j] * e;
            float To2 = 1.f, Te2 = sx, g = ac[0] * Te2;
#pragma unroll
            for (int i = 1; i < RHO; i++) {
                To2 = 2.f * sx * Te2 - To2;
                Te2 = 2.f * sx * To2 - Te2;
                g += ac[i] * Te2;
            }
            bf16 gh, gl; split2(g * xv, gh, gl);
            g_F_hi[fb + (1 + j) * DD + d] = gh;
            g_F_lo[fb + (1 + j) * DD + d] = gl;
        }
    }
}

// ---------------- mma.sync GEMM, BM=128 x BN=64, 128 threads, 2 smem stages ----------------
// 4 warps, warp tile 64x32 (wm: 64-row half, wn: 32-col half).
// TRANSA: A[k][m] rows=KC, 256B/row. else A[m][k] rows=128, 128B/row.
template <bool TRANSA>
__device__ __forceinline__ void loadA_async(u32 Abase, int k0, const bf16* Ah, const bf16* Al,
                                            int lda, int tid) {
#pragma unroll
    for (int half = 0; half < 2; half++) {
        const bf16* src = half ? Al : Ah;
        u32 ab = Abase + half * 16384;
#pragma unroll
        for (int i = 0; i < 8; i++) {
            int q = tid + i * 128;
            u32 dst; const char* g;
            if (TRANSA) {
                int row = q >> 4, ch = q & 15;   // 64 k-rows x 16 chunks (256B)
                g = (const char*)(src + (size_t)(k0 + row) * lda) + ch * 16;
                dst = ab + row * 256 + ((ch ^ (row & 7)) * 16);
            } else {
                int row = q >> 3, ch = q & 7;    // 128 m-rows x 8 chunks (128B)
                g = (const char*)(src + (size_t)row * lda + k0) + ch * 16;
                dst = ab + row * 128 + ((ch ^ (row & 7)) * 16);
            }
            asm volatile("cp.async.cg.shared.global [%0], [%1], 16;" :: "r"(dst), "l"(g));
        }
    }
}

__device__ __forceinline__ void loadB_async(u32 Bbase, int k0, const bf16* Bh, const bf16* Bl,
                                            int ldb, int tid) {
#pragma unroll
    for (int half = 0; half < 2; half++) {
        const bf16* src = half ? Bl : Bh;
        u32 bb = Bbase + half * 8192;
#pragma unroll
        for (int i = 0; i < 4; i++) {
            int q = tid + i * 128;
            int kr = q >> 3, ch = q & 7;
            const char* g = (const char*)(src + (size_t)(k0 + kr) * ldb) + ch * 16;
            u32 dst = bb + kr * 128 + ((ch ^ (kr & 7)) * 16);
            asm volatile("cp.async.cg.shared.global [%0], [%1], 16;" :: "r"(dst), "l"(g));
        }
    }
}

// OUTMODE: 0 = fp32 partial (C0/C1 by ks), 2 = bf16 hi/lo split output
template <bool TRANSA, int OUTMODE>
__global__ void __launch_bounds__(128, 2)
mma_gemm(const bf16* __restrict__ Ah, const bf16* __restrict__ Al,
         const bf16* __restrict__ Bh, const bf16* __restrict__ Bl,
         float* __restrict__ C0, float* __restrict__ C1,
         bf16* __restrict__ Zh, bf16* __restrict__ Zl,
         int nsplit, int K, int lda, int ldb, size_t aB, size_t bB, size_t cB) {
    extern __shared__ char smem[];
    u32 sb = smem_u32(smem);
    int tid = threadIdx.x, lane = tid & 31, wid = tid >> 5;
    int wm = wid & 1, wn = wid >> 1;
    int bx = blockIdx.x, nh = blockIdx.y;
    int bz = blockIdx.z / nsplit, ks = blockIdx.z - bz * nsplit;
    const int Klocal = K / nsplit;
    const int kofs = ks * Klocal;

    Ah += bz * aB; Al += bz * aB;
    if (TRANSA) { Ah += (size_t)kofs * lda + (size_t)bx * 128; Al += (size_t)kofs * lda + (size_t)bx * 128; }
    else        { Ah += (size_t)bx * 128 * lda + kofs;         Al += (size_t)bx * 128 * lda + kofs; }
    Bh += bz * bB + (size_t)kofs * ldb + (size_t)nh * 64;
    Bl += bz * bB + (size_t)kofs * ldb + (size_t)nh * 64;

    float acc[4][4][4];
#pragma unroll
    for (int a = 0; a < 4; a++)
#pragma unroll
        for (int b = 0; b < 4; b++)
#pragma unroll
            for (int c = 0; c < 4; c++) acc[a][b][c] = 0.f;

    const int NCH = Klocal / KC;

#pragma unroll
    for (int s = 0; s < 2; s++) {
        u32 Abase = sb + s * STAGE_B;
        loadA_async<TRANSA>(Abase, s * KC, Ah, Al, lda, tid);
        loadB_async(Abase + 32768, s * KC, Bh, Bl, ldb, tid);
        asm volatile("cp.async.commit_group;" ::: "memory");
    }

    for (int c = 0; c < NCH; c++) {
        int st = c & 1;
        if (c + 1 < NCH) asm volatile("cp.async.wait_group 1;" ::: "memory");
        else             asm volatile("cp.async.wait_group 0;" ::: "memory");
        __syncthreads();

        u32 Ab = sb + st * STAGE_B;
        u32 Bb = Ab + 32768;
#pragma unroll
        for (int s = 0; s < 4; s++) {
            u32 ah[4][4], al[4][4], bh[2][4], bl[2][4];
#pragma unroll
            for (int mt = 0; mt < 4; mt++) {
                u32 off;
                if (TRANSA) {
                    int kr = 16 * s + (lane & 7) + ((lane >> 4) << 3);
                    int mch = wm * 8 + mt * 2 + ((lane >> 3) & 1);
                    off = kr * 256 + ((mch ^ (kr & 7)) << 4);
                    ldsm4t(Ab + off, ah[mt]);
                    ldsm4t(Ab + 16384 + off, al[mt]);
                } else {
                    int row = wm * 64 + mt * 16 + (lane & 15);
                    int ch = 2 * s + (lane >> 4);
                    off = row * 128 + ((ch ^ (row & 7)) << 4);
                    ldsm4(Ab + off, ah[mt]);
                    ldsm4(Ab + 16384 + off, al[mt]);
                }
            }
#pragma unroll
            for (int nt = 0; nt < 2; nt++) {
                int kr = 16 * s + (lane & 7) + ((lane >> 3) & 1) * 8;
                int nch = wn * 4 + nt * 2 + (lane >> 4);
                u32 off = kr * 128 + ((nch ^ (kr & 7)) << 4);
                ldsm4t(Bb + off, bh[nt]);
                ldsm4t(Bb + 8192 + off, bl[nt]);
            }
#pragma unroll
            for (int mt = 0; mt < 4; mt++)
#pragma unroll
                for (int nt = 0; nt < 2; nt++)
#pragma unroll
                    for (int oc = 0; oc < 2; oc++) {
                        float* cc = acc[mt][nt * 2 + oc];
                        mma16816(cc, ah[mt], &bh[nt][oc * 2]);
                        mma16816(cc, ah[mt], &bl[nt][oc * 2]);
                        mma16816(cc, al[mt], &bh[nt][oc * 2]);
                    }
        }
        __syncthreads();
        if (c + 2 < NCH) {
            u32 Abase = sb + st * STAGE_B;
            loadA_async<TRANSA>(Abase, (c + 2) * KC, Ah, Al, lda, tid);
            loadB_async(Abase + 32768, (c + 2) * KC, Bh, Bl, ldb, tid);
            asm volatile("cp.async.commit_group;" ::: "memory");
        }
    }

    // epilogue
    float* C = (ks == 0) ? C0 : C1;
#pragma unroll
    for (int mt = 0; mt < 4; mt++)
#pragma unroll
        for (int j = 0; j < 4; j++) {
            int mloc = bx * 128 + wm * 64 + mt * 16 + (lane >> 2);
            int col = nh * 64 + wn * 32 + j * 8 + (lane & 3) * 2;
#pragma unroll
            for (int rr = 0; rr < 2; rr++) {
                float v0 = acc[mt][j][rr * 2], v1 = acc[mt][j][rr * 2 + 1];
                size_t off = (size_t)(mloc + rr * 8) * 128 + col;
                if (OUTMODE == 2) {
                    bf16 h0, l0, h1, l1;
                    split2(v0, h0, l0); split2(v1, h1, l1);
                    *(u32*)(Zh + bz * cB + off) = packb(h0, h1);
                    *(u32*)(Zl + bz * cB + off) = packb(l0, l1);
                } else {
                    *(float2*)(C + bz * cB + off) = make_float2(v0, v1);
                }
            }
        }
}

// ---------------------------------------------------------------
extern "C" void kernel_launch(void* const* d_in, const int* in_sizes, int n_in,
                              void* d_out, int out_size) {
    const float* eigvs = (const float*)d_in[0];
    const float* x = (const float*)d_in[1];
    const float* U = (const float*)d_in[2];
    const float* Wa = (const float*)d_in[3];
    const float* ba = (const float*)d_in[4];
    const float* Wb = (const float*)d_in[5];
    const float* bb = (const float*)d_in[6];
    const float* Ws = (const float*)d_in[7];
    const float* bs = (const float*)d_in[8];
    const float* WS_ = (const float*)d_in[9];
    const float* bS = (const float*)d_in[10];
    const float* WM = (const float*)d_in[11];
    const float* bM = (const float*)d_in[12];
    const float* Ww = (const float*)d_in[13];
    const float* bw = (const float*)d_in[14];
    float* out = (float*)d_out;

    cudaFuncSetAttribute(mma_gemm<true, 0>, cudaFuncAttributeMaxDynamicSharedMemorySize, SMEM_TOTAL);
    cudaFuncSetAttribute(mma_gemm<false, 2>, cudaFuncAttributeMaxDynamicSharedMemorySize, SMEM_TOTAL);
    cudaFuncSetAttribute(mma_gemm<false, 0>, cudaFuncAttributeMaxDynamicSharedMemorySize, SMEM_TOTAL);

    bf16 *pUh, *pUl, *pxh, *pxl, *pZh, *pZl, *pFh, *pFl, *pWh, *pWl;
    float *pcv, *pp0, *pp1;
    cudaGetSymbolAddress((void**)&pUh, g_U_hi);
    cudaGetSymbolAddress((void**)&pUl, g_U_lo);
    cudaGetSymbolAddress((void**)&pxh, g_x_hi);
    cudaGetSymbolAddress((void**)&pxl, g_x_lo);
    cudaGetSymbolAddress((void**)&pZh, g_Z_hi);
    cudaGetSymbolAddress((void**)&pZl, g_Z_lo);
    cudaGetSymbolAddress((void**)&pFh, g_F_hi);
    cudaGetSymbolAddress((void**)&pFl, g_F_lo);
    cudaGetSymbolAddress((void**)&pWh, g_Wc_hi);
    cudaGetSymbolAddress((void**)&pWl, g_Wc_lo);
    cudaGetSymbolAddress((void**)&pcv, g_cvec);
    cudaGetSymbolAddress((void**)&pp0, g_p0);
    cudaGetSymbolAddress((void**)&pp1, g_p1);

    const size_t sU = (size_t)NN * NN;
    const size_t sX = (size_t)NN * DD;

    convert_split_kernel<<<32768, 256>>>(U, pUh, pUl);
    convert_split_kernel<<<1024, 256>>>(x, pxh, pxl);
    partial_kernel<<<64, 128>>>(eigvs);

    // xt = U^T x : split-K=2 partials (combined inside fbuild)
    mma_gemm<true, 0><<<dim3(32, 2, 4), 128, SMEM_TOTAL>>>(
        pUh, pUl, pxh, pxl, pp0, pp1, nullptr, nullptr,
        2, NN, NN, DD, sU, sX, sX);

    weight_kernel<<<769, 128>>>(WS_, WM, Ww, bS, bM, bw);
    coeff_kernel<<<2, 128>>>(Wa, ba, Wb, bb, Ws, bs);
    fbuild_kernel<<<512, 128>>>(eigvs);

    // Z = F @ Wc : flat M=8192, K=768; unsplit; output split bf16
    mma_gemm<false, 2><<<dim3(64, 2, 1), 128, SMEM_TOTAL>>>(
        pFh, pFl, pWh, pWl, nullptr, nullptr, pZh, pZl,
        1, 6 * DD, 6 * DD, DD, 0, 0, 0);

    // out = U @ Z + cvec : split-K=2, partials then combine with bias
    mma_gemm<false, 0><<<dim3(32, 2, 4), 128, SMEM_TOTAL>>>(
        pUh, pUl, pZh, pZl, pp0, pp1, nullptr, nullptr,
        2, NN, NN, DD, sU, sX, sX);
    combine_bias_kernel<<<1024, 256>>>(pp0, pp1, pcv, out);
}

// round 12
// speedup vs baseline: 1.3950x; 1.2570x over previous
#include <cuda_runtime.h>
#include <cuda_bf16.h>
#include <cstdint>
#include <cstddef>

typedef __nv_bfloat16 bf16;
typedef unsigned int u32;

#define NN 4096
#define DD 128
#define NB 2
#define RHO 5
#define NJ 5
#define KC 64
#define STAGE_B16 32768     // bf16 gemm stage: A(hi+lo) 16K + B(hi+lo) 16K
#define STAGE_B32 32768     // tf32 gemm stage: A 16K + B 16K (fp32 64x64 tiles)
#define SMEM_TOTAL 65536
#define PARTN ((size_t)NB * NN * DD)

// ---------------- device scratch ----------------
__device__ float g_part[4 * PARTN];          // split-K partials (K=4)
__device__ float g_Z[PARTN];                 // gemm2 output, fp32
__device__ bf16 g_F_hi[(size_t)NB * NN * 6 * DD];
__device__ bf16 g_F_lo[(size_t)NB * NN * 6 * DD];
__device__ bf16 g_Wc_hi[6 * DD * DD];        // [768 k][128 d]
__device__ bf16 g_Wc_lo[6 * DD * DD];
__device__ float g_partial[NB * 32 * DD];
__device__ float g_acoef[NB * 8];
__device__ float g_bcoef[NB * 8];
__device__ float g_scale[NB * 8];
__device__ float g_cvec[DD];

// ---------------- helpers ----------------
__device__ __forceinline__ u32 smem_u32(const void* p) {
    u32 a;
    asm("{ .reg .u64 t; cvta.to.shared.u64 t, %1; cvt.u32.u64 %0, t; }" : "=r"(a) : "l"(p));
    return a;
}
__device__ __forceinline__ void split2(float v, bf16& h, bf16& l) {
    h = __float2bfloat16_rn(v);
    l = __float2bfloat16_rn(v - __bfloat162float(h));
}
__device__ __forceinline__ u32 packb(bf16 a, bf16 b) {
    return (u32)__bfloat16_as_ushort(a) | ((u32)__bfloat16_as_ushort(b) << 16);
}
__device__ __forceinline__ void ldsm4(u32 a, u32* r) {
    asm volatile("ldmatrix.sync.aligned.m8n8.x4.shared.b16 {%0,%1,%2,%3}, [%4];"
                 : "=r"(r[0]), "=r"(r[1]), "=r"(r[2]), "=r"(r[3]) : "r"(a));
}
__device__ __forceinline__ void ldsm4t(u32 a, u32* r) {
    asm volatile("ldmatrix.sync.aligned.m8n8.x4.trans.shared.b16 {%0,%1,%2,%3}, [%4];"
                 : "=r"(r[0]), "=r"(r[1]), "=r"(r[2]), "=r"(r[3]) : "r"(a));
}
__device__ __forceinline__ void mma16816(float* c, const u32* a, const u32* b) {
    asm volatile(
        "mma.sync.aligned.m16n8k16.row.col.f32.bf16.bf16.f32 "
        "{%0,%1,%2,%3}, {%4,%5,%6,%7}, {%8,%9}, {%0,%1,%2,%3};"
        : "+f"(c[0]), "+f"(c[1]), "+f"(c[2]), "+f"(c[3])
        : "r"(a[0]), "r"(a[1]), "r"(a[2]), "r"(a[3]), "r"(b[0]), "r"(b[1]));
}
__device__ __forceinline__ void mma1688t(float* c, const u32* a, const u32* b) {
    asm volatile(
        "mma.sync.aligned.m16n8k8.row.col.f32.tf32.tf32.f32 "
        "{%0,%1,%2,%3}, {%4,%5,%6,%7}, {%8,%9}, {%0,%1,%2,%3};"
        : "+f"(c[0]), "+f"(c[1]), "+f"(c[2]), "+f"(c[3])
        : "r"(a[0]), "r"(a[1]), "r"(a[2]), "r"(a[3]), "r"(b[0]), "r"(b[1]));
}
__device__ __forceinline__ float lds32(u32 a) {
    float v; asm volatile("ld.shared.f32 %0, [%1];" : "=f"(v) : "r"(a)); return v;
}
__device__ __forceinline__ u32 rna(float v) {
    u32 o; asm("cvt.rna.tf32.f32 %0, %1;" : "=r"(o) : "f"(v)); return o;
}

// ---------------- coefficient path ----------------
__global__ void partial_kernel(const float* __restrict__ eigvs) {
    int b = blockIdx.x >> 5, chunk = blockIdx.x & 31, d = threadIdx.x;
    const float* p = eigvs + ((size_t)b * NN + (size_t)chunk * 128) * DD + d;
    float s = 0.f;
#pragma unroll 8
    for (int r = 0; r < 128; r++) s += p[(size_t)r * DD];
    g_partial[(b * 32 + chunk) * DD + d] = s;
}

__global__ void coeff_kernel(const float* __restrict__ Wa, const float* __restrict__ ba,
                             const float* __restrict__ Wb, const float* __restrict__ bb,
                             const float* __restrict__ Ws, const float* __restrict__ bs) {
    __shared__ float red[15][128];
    int b = blockIdx.x, d = threadIdx.x;
    float s = 0.f;
    for (int c = 0; c < 32; c++) s += g_partial[(b * 32 + c) * DD + d];
    float m = s * (1.0f / NN);
#pragma unroll
    for (int j = 0; j < RHO; j++) {
        red[j][d] = m * Wa[d * RHO + j];
        red[5 + j][d] = m * Wb[d * RHO + j];
        red[10 + j][d] = m * Ws[d * NJ + j];
    }
    __syncthreads();
#pragma unroll
    for (int off = 64; off >= 1; off >>= 1) {
        for (int idx = d; idx < 15 * off; idx += 128) {
            int k = idx / off, e = idx - k * off;
            red[k][e] += red[k][e + off];
        }
        __syncthreads();
    }
    if (d < RHO) {
        g_acoef[b * 8 + d] = red[d][0] + ba[d];
        g_bcoef[b * 8 + d] = red[5 + d][0] + bb[d];
        float sv = red[10 + d][0] + bs[d];
        g_scale[b * 8 + d] = 5.0f / (1.0f + expf(-sv));
    }
}

__global__ void weight_kernel(const float* __restrict__ WS_, const float* __restrict__ WM,
                              const float* __restrict__ Ww, const float* __restrict__ bS,
                              const float* __restrict__ bM, const float* __restrict__ bw) {
    int blk = blockIdx.x, d = threadIdx.x;
    if (blk < 6 * DD) {
        int s = blk >> 7, i = blk & 127;
        const float* wsrc = (s == 0) ? (WS_ + i * DD) : (WM + (size_t)(s - 1) * DD * DD + i * DD);
        float acc = 0.f;
        for (int e = 0; e < DD; e++) acc += wsrc[e] * Ww[e * DD + d];
        bf16 h, l; split2(acc, h, l);
        g_Wc_hi[(size_t)blk * DD + d] = h;
        g_Wc_lo[(size_t)blk * DD + d] = l;
    } else {
        float acc = bw[d];
        for (int e = 0; e < DD; e++) {
            float cb = bS[e];
            for (int j = 0; j < NJ; j++) cb += bM[j * DD + e];
            acc += cb * Ww[e * DD + d];
        }
        g_cvec[d] = acc;
    }
}

// fbuild: xt = sum of 4 split-K partials (fixed order)
__global__ void fbuild_kernel(const float* __restrict__ eigvs) {
    int row0 = blockIdx.x * 16, d = threadIdx.x;
    for (int r = 0; r < 16; r++) {
        int row = row0 + r, b = row >> 12;
        const float* ac = g_acoef + b * 8;
        const float* bc = g_bcoef + b * 8;
        const float* sc = g_scale + b * 8;
        size_t idx = (size_t)row * DD + d;
        float e = eigvs[idx];
        float xv = (g_part[idx] + g_part[PARTN + idx]) +
                   (g_part[2 * PARTN + idx] + g_part[3 * PARTN + idx]);
        float To = 1.f, Te = e, h = bc[0];
#pragma unroll
        for (int i = 1; i < RHO; i++) {
            To = 2.f * e * Te - To;
            Te = 2.f * e * To - Te;
            h += bc[i] * To;
        }
        size_t fb = (size_t)row * (6 * DD);
        bf16 hh, hl; split2(h * xv, hh, hl);
        g_F_hi[fb + d] = hh; g_F_lo[fb + d] = hl;
#pragma unroll
        for (int j = 0; j < NJ; j++) {
            float sx = sc[j] * e;
            float To2 = 1.f, Te2 = sx, g = ac[0] * Te2;
#pragma unroll
            for (int i = 1; i < RHO; i++) {
                To2 = 2.f * sx * Te2 - To2;
                Te2 = 2.f * sx * To2 - Te2;
                g += ac[i] * Te2;
            }
            bf16 gh, gl; split2(g * xv, gh, gl);
            g_F_hi[fb + (1 + j) * DD + d] = gh;
            g_F_lo[fb + (1 + j) * DD + d] = gl;
        }
    }
}

// final: out = sum of 4 partials + bias
__global__ void combine4_bias_kernel(const float* __restrict__ bias, float* __restrict__ dst) {
    size_t i = (size_t)blockIdx.x * blockDim.x + threadIdx.x;
    int col = ((int)(i & 31)) * 4;
    const float4* p = (const float4*)g_part;
    const size_t q = PARTN / 4;
    float4 a = p[i], b = p[q + i], c = p[2 * q + i], d = p[3 * q + i];
    ((float4*)dst)[i] = make_float4((a.x + b.x) + (c.x + d.x) + bias[col],
                                    (a.y + b.y) + (c.y + d.y) + bias[col + 1],
                                    (a.z + b.z) + (c.z + d.z) + bias[col + 2],
                                    (a.w + b.w) + (c.w + d.w) + bias[col + 3]);
}

// ---------------- bf16 mma.sync GEMM (gemm2 only): BM=64 x BN=64, 128 thr, 2 stages ----------------
__device__ __forceinline__ void loadA16(u32 Abase, int k0, const bf16* Ah, const bf16* Al,
                                        int lda, int tid) {
#pragma unroll
    for (int half = 0; half < 2; half++) {
        const bf16* src = half ? Al : Ah;
        u32 ab = Abase + half * 8192;
#pragma unroll
        for (int i = 0; i < 4; i++) {
            int q = tid + i * 128;
            int row = q >> 3, ch = q & 7;
            const char* g = (const char*)(src + (size_t)row * lda + k0) + ch * 16;
            u32 dst = ab + row * 128 + ((ch ^ (row & 7)) * 16);
            asm volatile("cp.async.cg.shared.global [%0], [%1], 16;" :: "r"(dst), "l"(g));
        }
    }
}
__device__ __forceinline__ void loadB16(u32 Bbase, int k0, const bf16* Bh, const bf16* Bl,
                                        int ldb, int tid) {
#pragma unroll
    for (int half = 0; half < 2; half++) {
        const bf16* src = half ? Bl : Bh;
        u32 bb = Bbase + half * 8192;
#pragma unroll
        for (int i = 0; i < 4; i++) {
            int q = tid + i * 128;
            int kr = q >> 3, ch = q & 7;
            const char* g = (const char*)(src + (size_t)(k0 + kr) * ldb) + ch * 16;
            u32 dst = bb + kr * 128 + ((ch ^ (kr & 7)) * 16);
            asm volatile("cp.async.cg.shared.global [%0], [%1], 16;" :: "r"(dst), "l"(g));
        }
    }
}

__global__ void __launch_bounds__(128, 3)
bf16_gemm(const bf16* __restrict__ Ah, const bf16* __restrict__ Al,
          const bf16* __restrict__ Bh, const bf16* __restrict__ Bl,
          float* __restrict__ C, int K, int lda, int ldb) {
    extern __shared__ char smem[];
    u32 sb = smem_u32(smem);
    int tid = threadIdx.x, lane = tid & 31, wid = tid >> 5;
    int wm = wid & 1, wn = wid >> 1;
    int bx = blockIdx.x, nh = blockIdx.y;

    Ah += (size_t)bx * 64 * lda;
    Al += (size_t)bx * 64 * lda;
    Bh += (size_t)nh * 64;
    Bl += (size_t)nh * 64;

    float acc[2][4][4];
#pragma unroll
    for (int a = 0; a < 2; a++)
#pragma unroll
        for (int b = 0; b < 4; b++)
#pragma unroll
            for (int c = 0; c < 4; c++) acc[a][b][c] = 0.f;

    const int NCH = K / KC;
#pragma unroll
    for (int s = 0; s < 2; s++) {
        u32 Ab = sb + s * STAGE_B16;
        loadA16(Ab, s * KC, Ah, Al, lda, tid);
        loadB16(Ab + 16384, s * KC, Bh, Bl, ldb, tid);
        asm volatile("cp.async.commit_group;" ::: "memory");
    }

    for (int c = 0; c < NCH; c++) {
        int st = c & 1;
        if (c + 1 < NCH) asm volatile("cp.async.wait_group 1;" ::: "memory");
        else             asm volatile("cp.async.wait_group 0;" ::: "memory");
        __syncthreads();

        u32 Ab = sb + st * STAGE_B16;
        u32 Bb = Ab + 16384;
#pragma unroll
        for (int s = 0; s < 4; s++) {
            u32 ah[2][4], al[2][4], bh[2][4], bl[2][4];
#pragma unroll
            for (int mt = 0; mt < 2; mt++) {
                int row = wm * 32 + mt * 16 + (lane & 15);
                int ch = 2 * s + (lane >> 4);
                u32 off = row * 128 + ((ch ^ (row & 7)) << 4);
                ldsm4(Ab + off, ah[mt]);
                ldsm4(Ab + 8192 + off, al[mt]);
            }
#pragma unroll
            for (int nt = 0; nt < 2; nt++) {
                int kr = 16 * s + (lane & 7) + ((lane >> 3) & 1) * 8;
                int nch = wn * 4 + nt * 2 + (lane >> 4);
                u32 off = kr * 128 + ((nch ^ (kr & 7)) << 4);
                ldsm4t(Bb + off, bh[nt]);
                ldsm4t(Bb + 8192 + off, bl[nt]);
            }
#pragma unroll
            for (int mt = 0; mt < 2; mt++)
#pragma unroll
                for (int nt = 0; nt < 2; nt++)
#pragma unroll
                    for (int oc = 0; oc < 2; oc++) {
                        float* cc = acc[mt][nt * 2 + oc];
                        mma16816(cc, ah[mt], &bh[nt][oc * 2]);
                        mma16816(cc, ah[mt], &bl[nt][oc * 2]);
                        mma16816(cc, al[mt], &bh[nt][oc * 2]);
                    }
        }
        __syncthreads();
        if (c + 2 < NCH) {
            u32 Ab = sb + st * STAGE_B16;
            loadA16(Ab, (c + 2) * KC, Ah, Al, lda, tid);
            loadB16(Ab + 16384, (c + 2) * KC, Bh, Bl, ldb, tid);
            asm volatile("cp.async.commit_group;" ::: "memory");
        }
    }

#pragma unroll
    for (int mt = 0; mt < 2; mt++)
#pragma unroll
        for (int j = 0; j < 4; j++) {
            int mloc = bx * 64 + wm * 32 + mt * 16 + (lane >> 2);
            int col = nh * 64 + wn * 32 + j * 8 + (lane & 3) * 2;
#pragma unroll
            for (int rr = 0; rr < 2; rr++) {
                size_t off = (size_t)(mloc + rr * 8) * 128 + col;
                *(float2*)(C + off) = make_float2(acc[mt][j][rr * 2], acc[mt][j][rr * 2 + 1]);
            }
        }
}

// ---------------- tf32 GEMM: BM=64 x BN=64, 128 thr, 2 stages, split-K=4 ----------------
// smem tiles 64x64 fp32 (16KB), 256B rows, swizzle: chunk16 ^ ((row&7)<<1)
// TRANSA: smem A = gmem [k][m]; else [m][k]. B always [k][n].
template <bool TRANSA>
__device__ __forceinline__ void loadA32(u32 Ab, int k0, const float* A, int lda, int tid) {
#pragma unroll
    for (int i = 0; i < 8; i++) {
        int q = tid + i * 128;
        int row = q >> 4, ch = q & 15;
        const float* g;
        if (TRANSA) g = A + (size_t)(k0 + row) * lda + ch * 4;
        else        g = A + (size_t)row * lda + k0 + ch * 4;
        u32 dst = Ab + row * 256 + ((ch ^ ((row & 7) << 1)) << 4);
        asm volatile("cp.async.cg.shared.global [%0], [%1], 16;" :: "r"(dst), "l"(g));
    }
}
__device__ __forceinline__ void loadB32(u32 Bb, int k0, const float* B, int ldb, int tid) {
#pragma unroll
    for (int i = 0; i < 8; i++) {
        int q = tid + i * 128;
        int row = q >> 4, ch = q & 15;
        const float* g = B + (size_t)(k0 + row) * ldb + ch * 4;
        u32 dst = Bb + row * 256 + ((ch ^ ((row & 7) << 1)) << 4);
        asm volatile("cp.async.cg.shared.global [%0], [%1], 16;" :: "r"(dst), "l"(g));
    }
}

template <bool TRANSA>
__global__ void __launch_bounds__(128, 3)
tf32_gemm(const float* __restrict__ A, const float* __restrict__ B,
          float* __restrict__ Cpart, int K, int lda, int ldb,
          size_t aB, size_t bB) {
    extern __shared__ char smem[];
    u32 sb = smem_u32(smem);
    int tid = threadIdx.x, lane = tid & 31, wid = tid >> 5;
    int wm = wid & 1, wn = wid >> 1;
    int bx = blockIdx.x, nh = blockIdx.y;
    int bz = blockIdx.z >> 2, ks = blockIdx.z & 3;
    const int Klocal = K >> 2;
    const int kofs = ks * Klocal;

    A += bz * aB;
    if (TRANSA) A += (size_t)kofs * lda + (size_t)bx * 64;
    else        A += (size_t)bx * 64 * lda + kofs;
    B += bz * bB + (size_t)kofs * ldb + (size_t)nh * 64;
    float* C = Cpart + (size_t)ks * PARTN + (size_t)bz * NN * DD;

    float acc[2][4][4];
#pragma unroll
    for (int a = 0; a < 2; a++)
#pragma unroll
        for (int b = 0; b < 4; b++)
#pragma unroll
            for (int c = 0; c < 4; c++) acc[a][b][c] = 0.f;

    const int NCH = Klocal / KC;  // 16
#pragma unroll
    for (int s = 0; s < 2; s++) {
        u32 Ab = sb + s * STAGE_B32;
        loadA32<TRANSA>(Ab, s * KC, A, lda, tid);
        loadB32(Ab + 16384, s * KC, B, ldb, tid);
        asm volatile("cp.async.commit_group;" ::: "memory");
    }

    const int r = lane >> 2, c = lane & 3;

    for (int cc = 0; cc < NCH; cc++) {
        int st = cc & 1;
        if (cc + 1 < NCH) asm volatile("cp.async.wait_group 1;" ::: "memory");
        else              asm volatile("cp.async.wait_group 0;" ::: "memory");
        __syncthreads();

        u32 Ab = sb + st * STAGE_B32;
        u32 Bb = Ab + 16384;
#pragma unroll
        for (int s = 0; s < 8; s++) {
            u32 af[2][4], bf2[4][2];
#pragma unroll
            for (int mt = 0; mt < 2; mt++) {
                int mb = wm * 32 + mt * 16;
                if (TRANSA) {
                    // smem [k][m]; a: m=row of op, k=col of op
                    u32 base0 = Ab + (u32)(s * 8 + c) * 256;
                    u32 base1 = Ab + (u32)(s * 8 + c + 4) * 256;
                    int sw0 = c << 1, sw1 = (c + 4) << 1;
                    int mc0 = mb + r, mc1 = mb + r + 8;
                    af[mt][0] = rna(lds32(base0 + ((u32)((mc0 >> 2) ^ sw0) << 4) + ((mc0 & 3) << 2)));
                    af[mt][1] = rna(lds32(base0 + ((u32)((mc1 >> 2) ^ sw0) << 4) + ((mc1 & 3) << 2)));
                    af[mt][2] = rna(lds32(base1 + ((u32)((mc0 >> 2) ^ sw1) << 4) + ((mc0 & 3) << 2)));
                    af[mt][3] = rna(lds32(base1 + ((u32)((mc1 >> 2) ^ sw1) << 4) + ((mc1 & 3) << 2)));
                } else {
                    int row0 = mb + r, row1 = mb + r + 8;
                    int swr = (r & 7) << 1;   // row&7 == r for both row0,row1
                    u32 b0 = Ab + row0 * 256, b1 = Ab + row1 * 256;
                    int ch0 = (2 * s) ^ swr, ch1 = (2 * s + 1) ^ swr;
                    af[mt][0] = rna(lds32(b0 + (ch0 << 4) + (c << 2)));
                    af[mt][1] = rna(lds32(b1 + (ch0 << 4) + (c << 2)));
                    af[mt][2] = rna(lds32(b0 + (ch1 << 4) + (c << 2)));
                    af[mt][3] = rna(lds32(b1 + (ch1 << 4) + (c << 2)));
                }
            }
#pragma unroll
            for (int nf = 0; nf < 4; nf++) {
                int nb = wn * 32 + nf * 8;
                u32 base0 = Bb + (u32)(s * 8 + c) * 256;
                u32 base1 = Bb + (u32)(s * 8 + c + 4) * 256;
                int sw0 = c << 1, sw1 = (c + 4) << 1;
                int nn = nb + r;
                bf2[nf][0] = rna(lds32(base0 + ((u32)((nn >> 2) ^ sw0) << 4) + ((nn & 3) << 2)));
                bf2[nf][1] = rna(lds32(base1 + ((u32)((nn >> 2) ^ sw1) << 4) + ((nn & 3) << 2)));
            }
#pragma unroll
            for (int mt = 0; mt < 2; mt++)
#pragma unroll
                for (int nf = 0; nf < 4; nf++)
                    mma1688t(acc[mt][nf], af[mt], bf2[nf]);
        }
        __syncthreads();
        if (cc + 2 < NCH) {
            u32 Ab2 = sb + st * STAGE_B32;
            loadA32<TRANSA>(Ab2, (cc + 2) * KC, A, lda, tid);
            loadB32(Ab2 + 16384, (cc + 2) * KC, B, ldb, tid);
            asm volatile("cp.async.commit_group;" ::: "memory");
        }
    }

    // epilogue
#pragma unroll
    for (int mt = 0; mt < 2; mt++)
#pragma unroll
        for (int nf = 0; nf < 4; nf++) {
            int mloc = bx * 64 + wm * 32 + mt * 16 + r;
            int col = nh * 64 + wn * 32 + nf * 8 + c * 2;
#pragma unroll
            for (int rr = 0; rr < 2; rr++) {
                size_t off = (size_t)(mloc + rr * 8) * 128 + col;
                *(float2*)(C + off) = make_float2(acc[mt][nf][rr * 2], acc[mt][nf][rr * 2 + 1]);
            }
        }
}

// ---------------------------------------------------------------
extern "C" void kernel_launch(void* const* d_in, const int* in_sizes, int n_in,
                              void* d_out, int out_size) {
    const float* eigvs = (const float*)d_in[0];
    const float* x = (const float*)d_in[1];
    const float* U = (const float*)d_in[2];
    const float* Wa = (const float*)d_in[3];
    const float* ba = (const float*)d_in[4];
    const float* Wb = (const float*)d_in[5];
    const float* bb = (const float*)d_in[6];
    const float* Ws = (const float*)d_in[7];
    const float* bs = (const float*)d_in[8];
    const float* WS_ = (const float*)d_in[9];
    const float* bS = (const float*)d_in[10];
    const float* WM = (const float*)d_in[11];
    const float* bM = (const float*)d_in[12];
    const float* Ww = (const float*)d_in[13];
    const float* bw = (const float*)d_in[14];
    float* out = (float*)d_out;

    cudaFuncSetAttribute(tf32_gemm<true>, cudaFuncAttributeMaxDynamicSharedMemorySize, SMEM_TOTAL);
    cudaFuncSetAttribute(tf32_gemm<false>, cudaFuncAttributeMaxDynamicSharedMemorySize, SMEM_TOTAL);
    cudaFuncSetAttribute(bf16_gemm, cudaFuncAttributeMaxDynamicSharedMemorySize, SMEM_TOTAL);

    bf16 *pFh, *pFl, *pWh, *pWl;
    float *pcv, *pp, *pZ;
    cudaGetSymbolAddress((void**)&pFh, g_F_hi);
    cudaGetSymbolAddress((void**)&pFl, g_F_lo);
    cudaGetSymbolAddress((void**)&pWh, g_Wc_hi);
    cudaGetSymbolAddress((void**)&pWl, g_Wc_lo);
    cudaGetSymbolAddress((void**)&pcv, g_cvec);
    cudaGetSymbolAddress((void**)&pp, g_part);
    cudaGetSymbolAddress((void**)&pZ, g_Z);

    const size_t sU = (size_t)NN * NN;
    const size_t sX = (size_t)NN * DD;

    partial_kernel<<<64, 128>>>(eigvs);
    coeff_kernel<<<2, 128>>>(Wa, ba, Wb, bb, Ws, bs);
    weight_kernel<<<769, 128>>>(WS_, WM, Ww, bS, bM, bw);

    // gemm1: xt partials = U^T x  (tf32, A=U in [k][m] layout, split-K=4)
    tf32_gemm<true><<<dim3(64, 2, 8), 128, SMEM_TOTAL>>>(
        U, x, pp, NN, NN, DD, sU, sX);

    fbuild_kernel<<<512, 128>>>(eigvs);

    // gemm2: Z = F @ Wc (bf16 3-term, fp32 out)
    bf16_gemm<<<dim3(128, 2), 128, SMEM_TOTAL>>>(
        pFh, pFl, pWh, pWl, pZ, 6 * DD, 6 * DD, DD);

    // gemm3: out partials = U @ Z (tf32, split-K=4)
    tf32_gemm<false><<<dim3(64, 2, 8), 128, SMEM_TOTAL>>>(
        U, pZ, pp, NN, NN, DD, sU, sX);

    combine4_bias_kernel<<<1024, 256>>>(pcv, out);
}

// round 13
// speedup vs baseline: 1.5400x; 1.1039x over previous
#include <cuda_runtime.h>
#include <cuda_bf16.h>
#include <cstdint>
#include <cstddef>

typedef __nv_bfloat16 bf16;
typedef unsigned int u32;

#define NN 4096
#define DD 128
#define NB 2
#define RHO 5
#define NJ 5
#define KC 64
#define STAGE_B16 32768
#define STAGE_B32 32768
#define SMEM_TOTAL 65536
#define PARTN ((size_t)NB * NN * DD)

// ---------------- device scratch ----------------
__device__ float g_part[4 * PARTN];          // split-K partials (K=4)
__device__ float g_xT[(size_t)NB * DD * NN]; // x^T, tf32-rounded fp32
__device__ float g_ZT[(size_t)NB * DD * NN]; // Z^T, tf32-rounded fp32
__device__ bf16 g_F_hi[(size_t)NB * NN * 6 * DD];
__device__ bf16 g_F_lo[(size_t)NB * NN * 6 * DD];
__device__ bf16 g_Wc_hi[6 * DD * DD];
__device__ bf16 g_Wc_lo[6 * DD * DD];
__device__ float g_partial[NB * 32 * DD];
__device__ float g_acoef[NB * 8];
__device__ float g_bcoef[NB * 8];
__device__ float g_scale[NB * 8];
__device__ float g_cvec[DD];

// ---------------- helpers ----------------
__device__ __forceinline__ u32 smem_u32(const void* p) {
    u32 a;
    asm("{ .reg .u64 t; cvta.to.shared.u64 t, %1; cvt.u32.u64 %0, t; }" : "=r"(a) : "l"(p));
    return a;
}
__device__ __forceinline__ void split2(float v, bf16& h, bf16& l) {
    h = __float2bfloat16_rn(v);
    l = __float2bfloat16_rn(v - __bfloat162float(h));
}
__device__ __forceinline__ u32 packb(bf16 a, bf16 b) {
    return (u32)__bfloat16_as_ushort(a) | ((u32)__bfloat16_as_ushort(b) << 16);
}
__device__ __forceinline__ void ldsm4(u32 a, u32* r) {
    asm volatile("ldmatrix.sync.aligned.m8n8.x4.shared.b16 {%0,%1,%2,%3}, [%4];"
                 : "=r"(r[0]), "=r"(r[1]), "=r"(r[2]), "=r"(r[3]) : "r"(a));
}
__device__ __forceinline__ void ldsm4t(u32 a, u32* r) {
    asm volatile("ldmatrix.sync.aligned.m8n8.x4.trans.shared.b16 {%0,%1,%2,%3}, [%4];"
                 : "=r"(r[0]), "=r"(r[1]), "=r"(r[2]), "=r"(r[3]) : "r"(a));
}
__device__ __forceinline__ void mma16816(float* c, const u32* a, const u32* b) {
    asm volatile(
        "mma.sync.aligned.m16n8k16.row.col.f32.bf16.bf16.f32 "
        "{%0,%1,%2,%3}, {%4,%5,%6,%7}, {%8,%9}, {%0,%1,%2,%3};"
        : "+f"(c[0]), "+f"(c[1]), "+f"(c[2]), "+f"(c[3])
        : "r"(a[0]), "r"(a[1]), "r"(a[2]), "r"(a[3]), "r"(b[0]), "r"(b[1]));
}
__device__ __forceinline__ void mma1688t(float* c, const u32* a, const u32* b) {
    asm volatile(
        "mma.sync.aligned.m16n8k8.row.col.f32.tf32.tf32.f32 "
        "{%0,%1,%2,%3}, {%4,%5,%6,%7}, {%8,%9}, {%0,%1,%2,%3};"
        : "+f"(c[0]), "+f"(c[1]), "+f"(c[2]), "+f"(c[3])
        : "r"(a[0]), "r"(a[1]), "r"(a[2]), "r"(a[3]), "r"(b[0]), "r"(b[1]));
}
__device__ __forceinline__ float lds32(u32 a) {
    float v; asm volatile("ld.shared.f32 %0, [%1];" : "=f"(v) : "r"(a)); return v;
}
__device__ __forceinline__ u32 rna(float v) {
    u32 o; asm("cvt.rna.tf32.f32 %0, %1;" : "=r"(o) : "f"(v)); return o;
}

// ---------------- coefficient path ----------------
__global__ void partial_kernel(const float* __restrict__ eigvs) {
    int b = blockIdx.x >> 5, chunk = blockIdx.x & 31, d = threadIdx.x;
    const float* p = eigvs + ((size_t)b * NN + (size_t)chunk * 128) * DD + d;
    float s = 0.f;
#pragma unroll 8
    for (int r = 0; r < 128; r++) s += p[(size_t)r * DD];
    g_partial[(b * 32 + chunk) * DD + d] = s;
}

__global__ void coeff_kernel(const float* __restrict__ Wa, const float* __restrict__ ba,
                             const float* __restrict__ Wb, const float* __restrict__ bb,
                             const float* __restrict__ Ws, const float* __restrict__ bs) {
    __shared__ float red[15][128];
    int b = blockIdx.x, d = threadIdx.x;
    float s = 0.f;
    for (int c = 0; c < 32; c++) s += g_partial[(b * 32 + c) * DD + d];
    float m = s * (1.0f / NN);
#pragma unroll
    for (int j = 0; j < RHO; j++) {
        red[j][d] = m * Wa[d * RHO + j];
        red[5 + j][d] = m * Wb[d * RHO + j];
        red[10 + j][d] = m * Ws[d * NJ + j];
    }
    __syncthreads();
#pragma unroll
    for (int off = 64; off >= 1; off >>= 1) {
        for (int idx = d; idx < 15 * off; idx += 128) {
            int k = idx / off, e = idx - k * off;
            red[k][e] += red[k][e + off];
        }
        __syncthreads();
    }
    if (d < RHO) {
        g_acoef[b * 8 + d] = red[d][0] + ba[d];
        g_bcoef[b * 8 + d] = red[5 + d][0] + bb[d];
        float sv = red[10 + d][0] + bs[d];
        g_scale[b * 8 + d] = 5.0f / (1.0f + expf(-sv));
    }
}

__global__ void weight_kernel(const float* __restrict__ WS_, const float* __restrict__ WM,
                              const float* __restrict__ Ww, const float* __restrict__ bS,
                              const float* __restrict__ bM, const float* __restrict__ bw) {
    int blk = blockIdx.x, d = threadIdx.x;
    if (blk < 6 * DD) {
        int s = blk >> 7, i = blk & 127;
        const float* wsrc = (s == 0) ? (WS_ + i * DD) : (WM + (size_t)(s - 1) * DD * DD + i * DD);
        float acc = 0.f;
        for (int e = 0; e < DD; e++) acc += wsrc[e] * Ww[e * DD + d];
        bf16 h, l; split2(acc, h, l);
        g_Wc_hi[(size_t)blk * DD + d] = h;
        g_Wc_lo[(size_t)blk * DD + d] = l;
    } else {
        float acc = bw[d];
        for (int e = 0; e < DD; e++) {
            float cb = bS[e];
            for (int j = 0; j < NJ; j++) cb += bM[j * DD + e];
            acc += cb * Ww[e * DD + d];
        }
        g_cvec[d] = acc;
    }
}

// x -> x^T (tf32-rounded fp32)
__global__ void transpose_x_kernel(const float* __restrict__ x) {
    __shared__ float t[32][33];
    int tx = threadIdx.x, ty = threadIdx.y, b = blockIdx.z;
    int n0 = blockIdx.x * 32, d0 = blockIdx.y * 32;
#pragma unroll
    for (int j = 0; j < 4; j++)
        t[ty + 8 * j][tx] = x[((size_t)b * NN + n0 + ty + 8 * j) * DD + d0 + tx];
    __syncthreads();
#pragma unroll
    for (int j = 0; j < 4; j++)
        g_xT[(size_t)b * DD * NN + (size_t)(d0 + ty + 8 * j) * NN + n0 + tx] =
            __uint_as_float(rna(t[tx][ty + 8 * j]));
}

// fbuild: xt = sum of 4 split-K partials
__global__ void fbuild_kernel(const float* __restrict__ eigvs) {
    int row0 = blockIdx.x * 16, d = threadIdx.x;
    for (int r = 0; r < 16; r++) {
        int row = row0 + r, b = row >> 12;
        const float* ac = g_acoef + b * 8;
        const float* bc = g_bcoef + b * 8;
        const float* sc = g_scale + b * 8;
        size_t idx = (size_t)row * DD + d;
        float e = eigvs[idx];
        float xv = (g_part[idx] + g_part[PARTN + idx]) +
                   (g_part[2 * PARTN + idx] + g_part[3 * PARTN + idx]);
        float To = 1.f, Te = e, h = bc[0];
#pragma unroll
        for (int i = 1; i < RHO; i++) {
            To = 2.f * e * Te - To;
            Te = 2.f * e * To - Te;
            h += bc[i] * To;
        }
        size_t fb = (size_t)row * (6 * DD);
        bf16 hh, hl; split2(h * xv, hh, hl);
        g_F_hi[fb + d] = hh; g_F_lo[fb + d] = hl;
#pragma unroll
        for (int j = 0; j < NJ; j++) {
            float sx = sc[j] * e;
            float To2 = 1.f, Te2 = sx, g = ac[0] * Te2;
#pragma unroll
            for (int i = 1; i < RHO; i++) {
                To2 = 2.f * sx * Te2 - To2;
                Te2 = 2.f * sx * To2 - Te2;
                g += ac[i] * Te2;
            }
            bf16 gh, gl; split2(g * xv, gh, gl);
            g_F_hi[fb + (1 + j) * DD + d] = gh;
            g_F_lo[fb + (1 + j) * DD + d] = gl;
        }
    }
}

__global__ void combine4_bias_kernel(const float* __restrict__ bias, float* __restrict__ dst) {
    size_t i = (size_t)blockIdx.x * blockDim.x + threadIdx.x;
    int col = ((int)(i & 31)) * 4;
    const float4* p = (const float4*)g_part;
    const size_t q = PARTN / 4;
    float4 a = p[i], b = p[q + i], c = p[2 * q + i], d = p[3 * q + i];
    ((float4*)dst)[i] = make_float4((a.x + b.x) + (c.x + d.x) + bias[col],
                                    (a.y + b.y) + (c.y + d.y) + bias[col + 1],
                                    (a.z + b.z) + (c.z + d.z) + bias[col + 2],
                                    (a.w + b.w) + (c.w + d.w) + bias[col + 3]);
}

// ---------------- bf16 gemm2: Z^T output (rounded) ----------------
__device__ __forceinline__ void loadA16(u32 Abase, int k0, const bf16* Ah, const bf16* Al,
                                        int lda, int tid) {
#pragma unroll
    for (int half = 0; half < 2; half++) {
        const bf16* src = half ? Al : Ah;
        u32 ab = Abase + half * 8192;
#pragma unroll
        for (int i = 0; i < 4; i++) {
            int q = tid + i * 128;
            int row = q >> 3, ch = q & 7;
            const char* g = (const char*)(src + (size_t)row * lda + k0) + ch * 16;
            u32 dst = ab + row * 128 + ((ch ^ (row & 7)) * 16);
            asm volatile("cp.async.cg.shared.global [%0], [%1], 16;" :: "r"(dst), "l"(g));
        }
    }
}
__device__ __forceinline__ void loadB16(u32 Bbase, int k0, const bf16* Bh, const bf16* Bl,
                                        int ldb, int tid) {
#pragma unroll
    for (int half = 0; half < 2; half++) {
        const bf16* src = half ? Bl : Bh;
        u32 bb = Bbase + half * 8192;
#pragma unroll
        for (int i = 0; i < 4; i++) {
            int q = tid + i * 128;
            int kr = q >> 3, ch = q & 7;
            const char* g = (const char*)(src + (size_t)(k0 + kr) * ldb) + ch * 16;
            u32 dst = bb + kr * 128 + ((ch ^ (kr & 7)) * 16);
            asm volatile("cp.async.cg.shared.global [%0], [%1], 16;" :: "r"(dst), "l"(g));
        }
    }
}

__global__ void __launch_bounds__(128, 3)
bf16_gemm(const bf16* __restrict__ Ah, const bf16* __restrict__ Al,
          const bf16* __restrict__ Bh, const bf16* __restrict__ Bl,
          int K, int lda, int ldb) {
    extern __shared__ char smem[];
    u32 sb = smem_u32(smem);
    int tid = threadIdx.x, lane = tid & 31, wid = tid >> 5;
    int wm = wid & 1, wn = wid >> 1;
    int bx = blockIdx.x, nh = blockIdx.y;

    Ah += (size_t)bx * 64 * lda;
    Al += (size_t)bx * 64 * lda;
    Bh += (size_t)nh * 64;
    Bl += (size_t)nh * 64;

    float acc[2][4][4];
#pragma unroll
    for (int a = 0; a < 2; a++)
#pragma unroll
        for (int b = 0; b < 4; b++)
#pragma unroll
            for (int c = 0; c < 4; c++) acc[a][b][c] = 0.f;

    const int NCH = K / KC;
#pragma unroll
    for (int s = 0; s < 2; s++) {
        u32 Ab = sb + s * STAGE_B16;
        loadA16(Ab, s * KC, Ah, Al, lda, tid);
        loadB16(Ab + 16384, s * KC, Bh, Bl, ldb, tid);
        asm volatile("cp.async.commit_group;" ::: "memory");
    }

    for (int c = 0; c < NCH; c++) {
        int st = c & 1;
        if (c + 1 < NCH) asm volatile("cp.async.wait_group 1;" ::: "memory");
        else             asm volatile("cp.async.wait_group 0;" ::: "memory");
        __syncthreads();

        u32 Ab = sb + st * STAGE_B16;
        u32 Bb = Ab + 16384;
#pragma unroll
        for (int s = 0; s < 4; s++) {
            u32 ah[2][4], al[2][4], bh[2][4], bl[2][4];
#pragma unroll
            for (int mt = 0; mt < 2; mt++) {
                int row = wm * 32 + mt * 16 + (lane & 15);
                int ch = 2 * s + (lane >> 4);
                u32 off = row * 128 + ((ch ^ (row & 7)) << 4);
                ldsm4(Ab + off, ah[mt]);
                ldsm4(Ab + 8192 + off, al[mt]);
            }
#pragma unroll
            for (int nt = 0; nt < 2; nt++) {
                int kr = 16 * s + (lane & 7) + ((lane >> 3) & 1) * 8;
                int nch = wn * 4 + nt * 2 + (lane >> 4);
                u32 off = kr * 128 + ((nch ^ (kr & 7)) << 4);
                ldsm4t(Bb + off, bh[nt]);
                ldsm4t(Bb + 8192 + off, bl[nt]);
            }
#pragma unroll
            for (int mt = 0; mt < 2; mt++)
#pragma unroll
                for (int nt = 0; nt < 2; nt++)
#pragma unroll
                    for (int oc = 0; oc < 2; oc++) {
                        float* cc = acc[mt][nt * 2 + oc];
                        mma16816(cc, ah[mt], &bh[nt][oc * 2]);
                        mma16816(cc, ah[mt], &bl[nt][oc * 2]);
                        mma16816(cc, al[mt], &bh[nt][oc * 2]);
                    }
        }
        __syncthreads();
        if (c + 2 < NCH) {
            u32 Ab = sb + st * STAGE_B16;
            loadA16(Ab, (c + 2) * KC, Ah, Al, lda, tid);
            loadB16(Ab + 16384, (c + 2) * KC, Bh, Bl, ldb, tid);
            asm volatile("cp.async.commit_group;" ::: "memory");
        }
    }

    // epilogue: write Z^T (tf32-rounded) for gemm3 B operand
#pragma unroll
    for (int mt = 0; mt < 2; mt++)
#pragma unroll
        for (int j = 0; j < 4; j++) {
            int mloc = bx * 64 + wm * 32 + mt * 16 + (lane >> 2);
            int col = nh * 64 + wn * 32 + j * 8 + (lane & 3) * 2;
#pragma unroll
            for (int rr = 0; rr < 2; rr++) {
                int m = mloc + rr * 8;
                int b = m >> 12, n = m & 4095;
                size_t base = (size_t)b * DD * NN + n;
                g_ZT[base + (size_t)col * NN] = __uint_as_float(rna(acc[mt][j][rr * 2]));
                g_ZT[base + (size_t)(col + 1) * NN] = __uint_as_float(rna(acc[mt][j][rr * 2 + 1]));
            }
        }
}

// ---------------- tf32 GEMM loaders ----------------
// TRANSA A (gemm1): smem [k][m], 64 k-rows x 256B, swizzle ch^((k&7)<<1)
__device__ __forceinline__ void loadA32T(u32 Ab, int k0, const float* A, int lda, int tid) {
#pragma unroll
    for (int i = 0; i < 8; i++) {
        int q = tid + i * 128;
        int row = q >> 4, ch = q & 15;
        const float* g = A + (size_t)(k0 + row) * lda + ch * 4;
        u32 dst = Ab + row * 256 + ((ch ^ ((row & 7) << 1)) << 4);
        asm volatile("cp.async.cg.shared.global [%0], [%1], 16;" :: "r"(dst), "l"(g));
    }
}
// ldsm-layout tile: smem [r][k], 64 rows x 256B, swizzle ch^(row&15). A (gemm3) and B (both).
__device__ __forceinline__ void loadTile32(u32 Tb, int k0, const float* S, int lds, int tid) {
#pragma unroll
    for (int i = 0; i < 8; i++) {
        int q = tid + i * 128;
        int row = q >> 4, ch = q & 15;
        const float* g = S + (size_t)row * lds + k0 + ch * 4;
        u32 dst = Tb + row * 256 + ((ch ^ (row & 15)) << 4);
        asm volatile("cp.async.cg.shared.global [%0], [%1], 16;" :: "r"(dst), "l"(g));
    }
}

// B fragments via ldsm (pre-rounded source): 2 ldsm4 -> bf[4][2]
__device__ __forceinline__ void ldB32(u32 Bb, int s, int lane, int wn, u32 bf[4][2]) {
    int rbase = ((lane >> 4) << 3) + (lane & 7);
    int ch = 2 * s + ((lane >> 3) & 1);
#pragma unroll
    for (int half = 0; half < 2; half++) {
        int row = wn * 32 + half * 16 + rbase;
        u32 addr = Bb + row * 256 + ((ch ^ (row & 15)) << 4);
        u32 r[4];
        ldsm4(addr, r);
        bf[half * 2][0] = r[0]; bf[half * 2][1] = r[1];
        bf[half * 2 + 1][0] = r[2]; bf[half * 2 + 1][1] = r[3];
    }
}

// A fragments via ldsm (gemm3), with rna: 1 ldsm4 per mt
__device__ __forceinline__ void ldA32(u32 Ab2, int s, int lane, int wm, int mt, u32* af) {
    int row = wm * 32 + mt * 16 + ((lane >> 3) & 1) * 8 + (lane & 7);
    int ch = 2 * s + (lane >> 4);
    u32 addr = Ab2 + row * 256 + ((ch ^ (row & 15)) << 4);
    u32 r[4];
    ldsm4(addr, r);
#pragma unroll
    for (int j = 0; j < 4; j++) af[j] = rna(__uint_as_float(r[j]));
}

// ---------------- tf32 GEMM: BM=64 x BN=64, 128 thr, 2 stages, split-K=4 ----------------
template <bool TRANSA>
__global__ void __launch_bounds__(128, 3)
tf32_gemm(const float* __restrict__ A, const float* __restrict__ B,
          float* __restrict__ Cpart, int K, int lda, int ldb,
          size_t aB, size_t bB) {
    extern __shared__ char smem[];
    u32 sb = smem_u32(smem);
    int tid = threadIdx.x, lane = tid & 31, wid = tid >> 5;
    int wm = wid & 1, wn = wid >> 1;
    int bx = blockIdx.x, nh = blockIdx.y;
    int bz = blockIdx.z >> 2, ks = blockIdx.z & 3;
    const int Klocal = K >> 2;
    const int kofs = ks * Klocal;

    A += bz * aB;
    if (TRANSA) A += (size_t)kofs * lda + (size_t)bx * 64;
    else        A += (size_t)bx * 64 * lda + kofs;
    B += bz * bB + (size_t)(nh * 64) * ldb + kofs;
    float* C = Cpart + (size_t)ks * PARTN + (size_t)bz * NN * DD;

    float acc[2][4][4];
#pragma unroll
    for (int a = 0; a < 2; a++)
#pragma unroll
        for (int b = 0; b < 4; b++)
#pragma unroll
            for (int c = 0; c < 4; c++) acc[a][b][c] = 0.f;

    const int NCH = Klocal / KC;
#pragma unroll
    for (int s = 0; s < 2; s++) {
        u32 Ab = sb + s * STAGE_B32;
        if (TRANSA) loadA32T(Ab, s * KC, A, lda, tid);
        else        loadTile32(Ab, s * KC, A, lda, tid);
        loadTile32(Ab + 16384, s * KC, B, ldb, tid);
        asm volatile("cp.async.commit_group;" ::: "memory");
    }

    const int r = lane >> 2, c = lane & 3;

    for (int cc = 0; cc < NCH; cc++) {
        int st = cc & 1;
        if (cc + 1 < NCH) asm volatile("cp.async.wait_group 1;" ::: "memory");
        else              asm volatile("cp.async.wait_group 0;" ::: "memory");
        __syncthreads();

        u32 Ab = sb + st * STAGE_B32;
        u32 Bb = Ab + 16384;
#pragma unroll
        for (int s = 0; s < 8; s++) {
            u32 af[2][4], bf2[4][2];
            if (TRANSA) {
#pragma unroll
                for (int mt = 0; mt < 2; mt++) {
                    int mb = wm * 32 + mt * 16;
                    u32 base0 = Ab + (u32)(s * 8 + c) * 256;
                    u32 base1 = Ab + (u32)(s * 8 + c + 4) * 256;
                    int sw0 = c << 1, sw1 = (c + 4) << 1;
                    int mc0 = mb + r, mc1 = mb + r + 8;
                    af[mt][0] = rna(lds32(base0 + ((u32)((mc0 >> 2) ^ sw0) << 4) + ((mc0 & 3) << 2)));
                    af[mt][1] = rna(lds32(base0 + ((u32)((mc1 >> 2) ^ sw0) << 4) + ((mc1 & 3) << 2)));
                    af[mt][2] = rna(lds32(base1 + ((u32)((mc0 >> 2) ^ sw1) << 4) + ((mc0 & 3) << 2)));
                    af[mt][3] = rna(lds32(base1 + ((u32)((mc1 >> 2) ^ sw1) << 4) + ((mc1 & 3) << 2)));
                }
            } else {
#pragma unroll
                for (int mt = 0; mt < 2; mt++) ldA32(Ab, s, lane, wm, mt, af[mt]);
            }
            ldB32(Bb, s, lane, wn, bf2);
#pragma unroll
            for (int mt = 0; mt < 2; mt++)
#pragma unroll
                for (int nf = 0; nf < 4; nf++)
                    mma1688t(acc[mt][nf], af[mt], bf2[nf]);
        }
        __syncthreads();
        if (cc + 2 < NCH) {
            u32 Ab2 = sb + st * STAGE_B32;
            if (TRANSA) loadA32T(Ab2, (cc + 2) * KC, A, lda, tid);
            else        loadTile32(Ab2, (cc + 2) * KC, A, lda, tid);
            loadTile32(Ab2 + 16384, (cc + 2) * KC, B, ldb, tid);
            asm volatile("cp.async.commit_group;" ::: "memory");
        }
    }

    // epilogue
#pragma unroll
    for (int mt = 0; mt < 2; mt++)
#pragma unroll
        for (int nf = 0; nf < 4; nf++) {
            int mloc = bx * 64 + wm * 32 + mt * 16 + r;
            int col = nh * 64 + wn * 32 + nf * 8 + c * 2;
#pragma unroll
            for (int rr = 0; rr < 2; rr++) {
                size_t off = (size_t)(mloc + rr * 8) * 128 + col;
                *(float2*)(C + off) = make_float2(acc[mt][nf][rr * 2], acc[mt][nf][rr * 2 + 1]);
            }
        }
}

// ---------------------------------------------------------------
extern "C" void kernel_launch(void* const* d_in, const int* in_sizes, int n_in,
                              void* d_out, int out_size) {
    const float* eigvs = (const float*)d_in[0];
    const float* x = (const float*)d_in[1];
    const float* U = (const float*)d_in[2];
    const float* Wa = (const float*)d_in[3];
    const float* ba = (const float*)d_in[4];
    const float* Wb = (const float*)d_in[5];
    const float* bb = (const float*)d_in[6];
    const float* Ws = (const float*)d_in[7];
    const float* bs = (const float*)d_in[8];
    const float* WS_ = (const float*)d_in[9];
    const float* bS = (const float*)d_in[10];
    const float* WM = (const float*)d_in[11];
    const float* bM = (const float*)d_in[12];
    const float* Ww = (const float*)d_in[13];
    const float* bw = (const float*)d_in[14];
    float* out = (float*)d_out;

    cudaFuncSetAttribute(tf32_gemm<true>, cudaFuncAttributeMaxDynamicSharedMemorySize, SMEM_TOTAL);
    cudaFuncSetAttribute(tf32_gemm<false>, cudaFuncAttributeMaxDynamicSharedMemorySize, SMEM_TOTAL);
    cudaFuncSetAttribute(bf16_gemm, cudaFuncAttributeMaxDynamicSharedMemorySize, SMEM_TOTAL);

    bf16 *pFh, *pFl, *pWh, *pWl;
    float *pcv, *pp, *pxT, *pZT;
    cudaGetSymbolAddress((void**)&pFh, g_F_hi);
    cudaGetSymbolAddress((void**)&pFl, g_F_lo);
    cudaGetSymbolAddress((void**)&pWh, g_Wc_hi);
    cudaGetSymbolAddress((void**)&pWl, g_Wc_lo);
    cudaGetSymbolAddress((void**)&pcv, g_cvec);
    cudaGetSymbolAddress((void**)&pp, g_part);
    cudaGetSymbolAddress((void**)&pxT, g_xT);
    cudaGetSymbolAddress((void**)&pZT, g_ZT);

    const size_t sU = (size_t)NN * NN;
    const size_t sT = (size_t)DD * NN;

    partial_kernel<<<64, 128>>>(eigvs);
    coeff_kernel<<<2, 128>>>(Wa, ba, Wb, bb, Ws, bs);
    weight_kernel<<<769, 128>>>(WS_, WM, Ww, bS, bM, bw);
    transpose_x_kernel<<<dim3(128, 4, 2), dim3(32, 8)>>>(x);

    // gemm1: xt[n][d] = sum_k U[k][n] x[k][d]; A=U^T (scalar A path), B=xT (ldsm)
    tf32_gemm<true><<<dim3(64, 2, 8), 128, SMEM_TOTAL>>>(
        U, pxT, pp, NN, NN, NN, sU, sT);

    fbuild_kernel<<<512, 128>>>(eigvs);

    // gemm2: Z^T = (F @ Wc)^T (bf16 3-term, transposed rounded epilogue)
    bf16_gemm<<<dim3(128, 2), 128, SMEM_TOTAL>>>(
        pFh, pFl, pWh, pWl, 6 * DD, 6 * DD, DD);

    // gemm3: out[r][e] = sum_m U[r][m] Z[m][e]; A=U (ldsm), B=ZT (ldsm)
    tf32_gemm<false><<<dim3(64, 2, 8), 128, SMEM_TOTAL>>>(
        U, pZT, pp, NN, NN, NN, sU, sT);

    combine4_bias_kernel<<<1024, 256>>>(pcv, out);
}

// round 14
// speedup vs baseline: 1.5937x; 1.0349x over previous
#include <cuda_runtime.h>
#include <cstdint>
#include <cstddef>

typedef unsigned int u32;

#define NN 4096
#define DD 128
#define NB 2
#define RHO 5
#define NJ 5
#define KC 64
#define STAGE_B32 32768
#define SMEM_TOTAL 65536
#define PARTN ((size_t)NB * NN * DD)

// ---------------- device scratch ----------------
__device__ float g_part[4 * PARTN];            // split-K partials (K=4)
__device__ float g_xT[(size_t)NB * DD * NN];   // x^T, tf32-rounded fp32
__device__ float g_ZT[(size_t)NB * DD * NN];   // Z^T, tf32-rounded fp32
__device__ float g_F32[(size_t)NB * NN * 6 * DD]; // F, tf32-rounded fp32 [8192][768]
__device__ float g_WcT[DD * 6 * DD];           // Wc^T [128 d][768 k], tf32-rounded
__device__ float g_partial[NB * 32 * DD];
__device__ float g_acoef[NB * 8];
__device__ float g_bcoef[NB * 8];
__device__ float g_scale[NB * 8];
__device__ float g_cvec[DD];

// ---------------- helpers ----------------
__device__ __forceinline__ u32 smem_u32(const void* p) {
    u32 a;
    asm("{ .reg .u64 t; cvta.to.shared.u64 t, %1; cvt.u32.u64 %0, t; }" : "=r"(a) : "l"(p));
    return a;
}
__device__ __forceinline__ void ldsm4(u32 a, u32* r) {
    asm volatile("ldmatrix.sync.aligned.m8n8.x4.shared.b16 {%0,%1,%2,%3}, [%4];"
                 : "=r"(r[0]), "=r"(r[1]), "=r"(r[2]), "=r"(r[3]) : "r"(a));
}
__device__ __forceinline__ void mma1688t(float* c, const u32* a, const u32* b) {
    asm volatile(
        "mma.sync.aligned.m16n8k8.row.col.f32.tf32.tf32.f32 "
        "{%0,%1,%2,%3}, {%4,%5,%6,%7}, {%8,%9}, {%0,%1,%2,%3};"
        : "+f"(c[0]), "+f"(c[1]), "+f"(c[2]), "+f"(c[3])
        : "r"(a[0]), "r"(a[1]), "r"(a[2]), "r"(a[3]), "r"(b[0]), "r"(b[1]));
}
__device__ __forceinline__ float lds32(u32 a) {
    float v; asm volatile("ld.shared.f32 %0, [%1];" : "=f"(v) : "r"(a)); return v;
}
__device__ __forceinline__ u32 rna(float v) {
    u32 o; asm("cvt.rna.tf32.f32 %0, %1;" : "=r"(o) : "f"(v)); return o;
}
__device__ __forceinline__ float rnaf(float v) { return __uint_as_float(rna(v)); }

// ---------------- coefficient path ----------------
__global__ void partial_kernel(const float* __restrict__ eigvs) {
    int b = blockIdx.x >> 5, chunk = blockIdx.x & 31, d = threadIdx.x;
    const float* p = eigvs + ((size_t)b * NN + (size_t)chunk * 128) * DD + d;
    float s = 0.f;
#pragma unroll 8
    for (int r = 0; r < 128; r++) s += p[(size_t)r * DD];
    g_partial[(b * 32 + chunk) * DD + d] = s;
}

__global__ void coeff_kernel(const float* __restrict__ Wa, const float* __restrict__ ba,
                             const float* __restrict__ Wb, const float* __restrict__ bb,
                             const float* __restrict__ Ws, const float* __restrict__ bs) {
    __shared__ float red[15][128];
    int b = blockIdx.x, d = threadIdx.x;
    float s = 0.f;
    for (int c = 0; c < 32; c++) s += g_partial[(b * 32 + c) * DD + d];
    float m = s * (1.0f / NN);
#pragma unroll
    for (int j = 0; j < RHO; j++) {
        red[j][d] = m * Wa[d * RHO + j];
        red[5 + j][d] = m * Wb[d * RHO + j];
        red[10 + j][d] = m * Ws[d * NJ + j];
    }
    __syncthreads();
#pragma unroll
    for (int off = 64; off >= 1; off >>= 1) {
        for (int idx = d; idx < 15 * off; idx += 128) {
            int k = idx / off, e = idx - k * off;
            red[k][e] += red[k][e + off];
        }
        __syncthreads();
    }
    if (d < RHO) {
        g_acoef[b * 8 + d] = red[d][0] + ba[d];
        g_bcoef[b * 8 + d] = red[5 + d][0] + bb[d];
        float sv = red[10 + d][0] + bs[d];
        g_scale[b * 8 + d] = 5.0f / (1.0f + expf(-sv));
    }
}

// fold channel mats through Ww; output Wc^T [d][768] tf32-rounded
__global__ void weight_kernel(const float* __restrict__ WS_, const float* __restrict__ WM,
                              const float* __restrict__ Ww, const float* __restrict__ bS,
                              const float* __restrict__ bM, const float* __restrict__ bw) {
    int blk = blockIdx.x, d = threadIdx.x;
    if (blk < 6 * DD) {
        int s = blk >> 7, i = blk & 127;
        const float* wsrc = (s == 0) ? (WS_ + i * DD) : (WM + (size_t)(s - 1) * DD * DD + i * DD);
        float acc = 0.f;
        for (int e = 0; e < DD; e++) acc += wsrc[e] * Ww[e * DD + d];
        g_WcT[(size_t)d * (6 * DD) + blk] = rnaf(acc);
    } else {
        float acc = bw[d];
        for (int e = 0; e < DD; e++) {
            float cb = bS[e];
            for (int j = 0; j < NJ; j++) cb += bM[j * DD + e];
            acc += cb * Ww[e * DD + d];
        }
        g_cvec[d] = acc;
    }
}

// x -> x^T (tf32-rounded fp32)
__global__ void transpose_x_kernel(const float* __restrict__ x) {
    __shared__ float t[32][33];
    int tx = threadIdx.x, ty = threadIdx.y, b = blockIdx.z;
    int n0 = blockIdx.x * 32, d0 = blockIdx.y * 32;
#pragma unroll
    for (int j = 0; j < 4; j++)
        t[ty + 8 * j][tx] = x[((size_t)b * NN + n0 + ty + 8 * j) * DD + d0 + tx];
    __syncthreads();
#pragma unroll
    for (int j = 0; j < 4; j++)
        g_xT[(size_t)b * DD * NN + (size_t)(d0 + ty + 8 * j) * NN + n0 + tx] =
            rnaf(t[tx][ty + 8 * j]);
}

// fbuild: xt = sum of 4 split-K partials; F output tf32-rounded fp32
__global__ void fbuild_kernel(const float* __restrict__ eigvs) {
    int row0 = blockIdx.x * 16, d = threadIdx.x;
    for (int r = 0; r < 16; r++) {
        int row = row0 + r, b = row >> 12;
        const float* ac = g_acoef + b * 8;
        const float* bc = g_bcoef + b * 8;
        const float* sc = g_scale + b * 8;
        size_t idx = (size_t)row * DD + d;
        float e = eigvs[idx];
        float xv = (g_part[idx] + g_part[PARTN + idx]) +
                   (g_part[2 * PARTN + idx] + g_part[3 * PARTN + idx]);
        float To = 1.f, Te = e, h = bc[0];
#pragma unroll
        for (int i = 1; i < RHO; i++) {
            To = 2.f * e * Te - To;
            Te = 2.f * e * To - Te;
            h += bc[i] * To;
        }
        size_t fb = (size_t)row * (6 * DD);
        g_F32[fb + d] = rnaf(h * xv);
#pragma unroll
        for (int j = 0; j < NJ; j++) {
            float sx = sc[j] * e;
            float To2 = 1.f, Te2 = sx, g = ac[0] * Te2;
#pragma unroll
            for (int i = 1; i < RHO; i++) {
                To2 = 2.f * sx * Te2 - To2;
                Te2 = 2.f * sx * To2 - Te2;
                g += ac[i] * Te2;
            }
            g_F32[fb + (1 + j) * DD + d] = rnaf(g * xv);
        }
    }
}

__global__ void combine4_bias_kernel(const float* __restrict__ bias, float* __restrict__ dst) {
    size_t i = (size_t)blockIdx.x * blockDim.x + threadIdx.x;
    int col = ((int)(i & 31)) * 4;
    const float4* p = (const float4*)g_part;
    const size_t q = PARTN / 4;
    float4 a = p[i], b = p[q + i], c = p[2 * q + i], d = p[3 * q + i];
    ((float4*)dst)[i] = make_float4((a.x + b.x) + (c.x + d.x) + bias[col],
                                    (a.y + b.y) + (c.y + d.y) + bias[col + 1],
                                    (a.z + b.z) + (c.z + d.z) + bias[col + 2],
                                    (a.w + b.w) + (c.w + d.w) + bias[col + 3]);
}

// ---------------- tf32 GEMM loaders ----------------
// TRANSA A (gemm1): smem [k][m], 64 k-rows x 256B, swizzle ch^((k&7)<<1)
__device__ __forceinline__ void loadA32T(u32 Ab, int k0, const float* A, int lda, int tid) {
#pragma unroll
    for (int i = 0; i < 8; i++) {
        int q = tid + i * 128;
        int row = q >> 4, ch = q & 15;
        const float* g = A + (size_t)(k0 + row) * lda + ch * 4;
        u32 dst = Ab + row * 256 + ((ch ^ ((row & 7) << 1)) << 4);
        asm volatile("cp.async.cg.shared.global [%0], [%1], 16;" :: "r"(dst), "l"(g));
    }
}
// ldsm-layout tile: smem [r][k], 64 rows x 256B, swizzle ch^(row&15)
__device__ __forceinline__ void loadTile32(u32 Tb, int k0, const float* S, int lds, int tid) {
#pragma unroll
    for (int i = 0; i < 8; i++) {
        int q = tid + i * 128;
        int row = q >> 4, ch = q & 15;
        const float* g = S + (size_t)row * lds + k0 + ch * 4;
        u32 dst = Tb + row * 256 + ((ch ^ (row & 15)) << 4);
        asm volatile("cp.async.cg.shared.global [%0], [%1], 16;" :: "r"(dst), "l"(g));
    }
}

// B fragments via ldsm (pre-rounded source): 2 ldsm4 -> bf[4][2]
__device__ __forceinline__ void ldB32(u32 Bb, int s, int lane, int wn, u32 bf[4][2]) {
    int rbase = ((lane >> 4) << 3) + (lane & 7);
    int ch = 2 * s + ((lane >> 3) & 1);
#pragma unroll
    for (int half = 0; half < 2; half++) {
        int row = wn * 32 + half * 16 + rbase;
        u32 addr = Bb + row * 256 + ((ch ^ (row & 15)) << 4);
        u32 r[4];
        ldsm4(addr, r);
        bf[half * 2][0] = r[0]; bf[half * 2][1] = r[1];
        bf[half * 2 + 1][0] = r[2]; bf[half * 2 + 1][1] = r[3];
    }
}

// A fragments via ldsm; CVTA: apply rna (raw fp32 source) or not (pre-rounded)
template <bool CVTA>
__device__ __forceinline__ void ldA32(u32 Ab2, int s, int lane, int wm, int mt, u32* af) {
    int row = wm * 32 + mt * 16 + ((lane >> 3) & 1) * 8 + (lane & 7);
    int ch = 2 * s + (lane >> 4);
    u32 addr = Ab2 + row * 256 + ((ch ^ (row & 15)) << 4);
    u32 r[4];
    ldsm4(addr, r);
#pragma unroll
    for (int j = 0; j < 4; j++) af[j] = CVTA ? rna(__uint_as_float(r[j])) : r[j];
}

// ---------------- tf32 GEMM: BM=64 x BN=64, 128 thr, 2 stages ----------------
// OUTMODE 0: fp32 split-K partial [m][128]; OUTMODE 1: Z^T rounded transposed
template <bool TRANSA, bool CVTA, int OUTMODE, int NSPLIT>
__global__ void __launch_bounds__(128, 3)
tf32_gemm(const float* __restrict__ A, const float* __restrict__ B,
          float* __restrict__ Cpart, int K, int lda, int ldb,
          size_t aB, size_t bB) {
    extern __shared__ char smem[];
    u32 sb = smem_u32(smem);
    int tid = threadIdx.x, lane = tid & 31, wid = tid >> 5;
    int wm = wid & 1, wn = wid >> 1;
    int bx = blockIdx.x, nh = blockIdx.y;
    int bz = blockIdx.z / NSPLIT, ks = blockIdx.z % NSPLIT;
    const int Klocal = K / NSPLIT;
    const int kofs = ks * Klocal;

    A += bz * aB;
    if (TRANSA) A += (size_t)kofs * lda + (size_t)bx * 64;
    else        A += (size_t)bx * 64 * lda + kofs;
    B += bz * bB + (size_t)(nh * 64) * ldb + kofs;
    float* C = Cpart + (size_t)ks * PARTN + (size_t)bz * NN * DD;

    float acc[2][4][4];
#pragma unroll
    for (int a = 0; a < 2; a++)
#pragma unroll
        for (int b = 0; b < 4; b++)
#pragma unroll
            for (int c = 0; c < 4; c++) acc[a][b][c] = 0.f;

    const int NCH = Klocal / KC;
#pragma unroll
    for (int s = 0; s < 2; s++) {
        u32 Ab = sb + s * STAGE_B32;
        if (TRANSA) loadA32T(Ab, s * KC, A, lda, tid);
        else        loadTile32(Ab, s * KC, A, lda, tid);
        loadTile32(Ab + 16384, s * KC, B, ldb, tid);
        asm volatile("cp.async.commit_group;" ::: "memory");
    }

    const int r = lane >> 2, c = lane & 3;

    // hoisted scalar-A swizzle offsets (TRANSA path): loop-invariant per thread
    u32 aoff[2][4];
    if (TRANSA) {
        int sw0 = c << 1, sw1 = (c + 4) << 1;
#pragma unroll
        for (int mt = 0; mt < 2; mt++) {
            int mb = wm * 32 + mt * 16;
            int mc0 = mb + r, mc1 = mb + r + 8;
            aoff[mt][0] = ((u32)((mc0 >> 2) ^ sw0) << 4) + ((mc0 & 3) << 2);
            aoff[mt][1] = ((u32)((mc1 >> 2) ^ sw0) << 4) + ((mc1 & 3) << 2);
            aoff[mt][2] = 1024u + ((u32)((mc0 >> 2) ^ sw1) << 4) + ((mc0 & 3) << 2);
            aoff[mt][3] = 1024u + ((u32)((mc1 >> 2) ^ sw1) << 4) + ((mc1 & 3) << 2);
        }
    }

    for (int cc = 0; cc < NCH; cc++) {
        int st = cc & 1;
        if (cc + 1 < NCH) asm volatile("cp.async.wait_group 1;" ::: "memory");
        else              asm volatile("cp.async.wait_group 0;" ::: "memory");
        __syncthreads();

        u32 Ab = sb + st * STAGE_B32;
        u32 Bb = Ab + 16384;
#pragma unroll
        for (int s = 0; s < 8; s++) {
            u32 af[2][4], bf2[4][2];
            if (TRANSA) {
                u32 base = Ab + (u32)(s * 8 + c) * 256;
#pragma unroll
                for (int mt = 0; mt < 2; mt++) {
                    af[mt][0] = rna(lds32(base + aoff[mt][0]));
                    af[mt][1] = rna(lds32(base + aoff[mt][1]));
                    af[mt][2] = rna(lds32(base + aoff[mt][2]));
                    af[mt][3] = rna(lds32(base + aoff[mt][3]));
                }
            } else {
#pragma unroll
                for (int mt = 0; mt < 2; mt++) ldA32<CVTA>(Ab, s, lane, wm, mt, af[mt]);
            }
            ldB32(Bb, s, lane, wn, bf2);
#pragma unroll
            for (int mt = 0; mt < 2; mt++)
#pragma unroll
                for (int nf = 0; nf < 4; nf++)
                    mma1688t(acc[mt][nf], af[mt], bf2[nf]);
        }
        __syncthreads();
        if (cc + 2 < NCH) {
            u32 Ab2 = sb + st * STAGE_B32;
            if (TRANSA) loadA32T(Ab2, (cc + 2) * KC, A, lda, tid);
            else        loadTile32(Ab2, (cc + 2) * KC, A, lda, tid);
            loadTile32(Ab2 + 16384, (cc + 2) * KC, B, ldb, tid);
            asm volatile("cp.async.commit_group;" ::: "memory");
        }
    }

    // epilogue
#pragma unroll
    for (int mt = 0; mt < 2; mt++)
#pragma unroll
        for (int nf = 0; nf < 4; nf++) {
            int mloc = bx * 64 + wm * 32 + mt * 16 + r;
            int col = nh * 64 + wn * 32 + nf * 8 + c * 2;
#pragma unroll
            for (int rr = 0; rr < 2; rr++) {
                if (OUTMODE == 0) {
                    size_t off = (size_t)(mloc + rr * 8) * 128 + col;
                    *(float2*)(C + off) = make_float2(acc[mt][nf][rr * 2], acc[mt][nf][rr * 2 + 1]);
                } else {
                    int m = mloc + rr * 8;
                    int b = m >> 12, n = m & 4095;
                    size_t base = (size_t)b * DD * NN + n;
                    g_ZT[base + (size_t)col * NN] = rnaf(acc[mt][nf][rr * 2]);
                    g_ZT[base + (size_t)(col + 1) * NN] = rnaf(acc[mt][nf][rr * 2 + 1]);
                }
            }
        }
}

// ---------------------------------------------------------------
extern "C" void kernel_launch(void* const* d_in, const int* in_sizes, int n_in,
                              void* d_out, int out_size) {
    const float* eigvs = (const float*)d_in[0];
    const float* x = (const float*)d_in[1];
    const float* U = (const float*)d_in[2];
    const float* Wa = (const float*)d_in[3];
    const float* ba = (const float*)d_in[4];
    const float* Wb = (const float*)d_in[5];
    const float* bb = (const float*)d_in[6];
    const float* Ws = (const float*)d_in[7];
    const float* bs = (const float*)d_in[8];
    const float* WS_ = (const float*)d_in[9];
    const float* bS = (const float*)d_in[10];
    const float* WM = (const float*)d_in[11];
    const float* bM = (const float*)d_in[12];
    const float* Ww = (const float*)d_in[13];
    const float* bw = (const float*)d_in[14];
    float* out = (float*)d_out;

    cudaFuncSetAttribute(tf32_gemm<true, true, 0, 4>, cudaFuncAttributeMaxDynamicSharedMemorySize, SMEM_TOTAL);
    cudaFuncSetAttribute(tf32_gemm<false, true, 0, 4>, cudaFuncAttributeMaxDynamicSharedMemorySize, SMEM_TOTAL);
    cudaFuncSetAttribute(tf32_gemm<false, false, 1, 1>, cudaFuncAttributeMaxDynamicSharedMemorySize, SMEM_TOTAL);

    float *pcv, *pp, *pxT, *pZT, *pF, *pW;
    cudaGetSymbolAddress((void**)&pcv, g_cvec);
    cudaGetSymbolAddress((void**)&pp, g_part);
    cudaGetSymbolAddress((void**)&pxT, g_xT);
    cudaGetSymbolAddress((void**)&pZT, g_ZT);
    cudaGetSymbolAddress((void**)&pF, g_F32);
    cudaGetSymbolAddress((void**)&pW, g_WcT);

    const size_t sU = (size_t)NN * NN;
    const size_t sT = (size_t)DD * NN;

    partial_kernel<<<64, 128>>>(eigvs);
    coeff_kernel<<<2, 128>>>(Wa, ba, Wb, bb, Ws, bs);
    weight_kernel<<<769, 128>>>(WS_, WM, Ww, bS, bM, bw);
    transpose_x_kernel<<<dim3(128, 4, 2), dim3(32, 8)>>>(x);

    // gemm1: xt[n][d] = sum_k U[k][n] x[k][d]; A=U^T (scalar, cvt), B=xT (ldsm, pre-rounded)
    tf32_gemm<true, true, 0, 4><<<dim3(64, 2, 8), 128, SMEM_TOTAL>>>(
        U, pxT, pp, NN, NN, NN, sU, sT);

    fbuild_kernel<<<512, 128>>>(eigvs);

    // gemm2: Z^T = (F @ Wc)^T; A=F (ldsm, pre-rounded), B=WcT (ldsm, pre-rounded), K=768
    tf32_gemm<false, false, 1, 1><<<dim3(128, 2, 1), 128, SMEM_TOTAL>>>(
        pF, pW, nullptr, 6 * DD, 6 * DD, 6 * DD, 0, 0);

    // gemm3: out[r][e] = sum_m U[r][m] Z[m][e]; A=U (ldsm, cvt), B=ZT (ldsm, pre-rounded)
    tf32_gemm<false, true, 0, 4><<<dim3(64, 2, 8), 128, SMEM_TOTAL>>>(
        U, pZT, pp, NN, NN, NN, sU, sT);

    combine4_bias_kernel<<<1024, 256>>>(pcv, out);
}

// round 15
// speedup vs baseline: 1.6131x; 1.0122x over previous
#include <cuda_runtime.h>
#include <cstdint>
#include <cstddef>

typedef unsigned int u32;

#define NN 4096
#define DD 128
#define NB 2
#define RHO 5
#define NJ 5
#define KC 64
#define PARTN ((size_t)NB * NN * DD)

// ---------------- device scratch ----------------
__device__ float g_part[2 * PARTN];            // split-K partials (K=2)
__device__ float g_xT[(size_t)NB * DD * NN];   // x^T, tf32-rounded fp32
__device__ float g_ZT[(size_t)NB * DD * NN];   // Z^T, tf32-rounded fp32
__device__ float g_F32[(size_t)NB * NN * 6 * DD]; // F, tf32-rounded fp32 [8192][768]
__device__ float g_WcT[DD * 6 * DD];           // Wc^T [128 d][768 k], tf32-rounded
__device__ float g_partial[NB * 32 * DD];
__device__ float g_acoef[NB * 8];
__device__ float g_bcoef[NB * 8];
__device__ float g_scale[NB * 8];
__device__ float g_cvec[DD];

// ---------------- helpers ----------------
__device__ __forceinline__ u32 smem_u32(const void* p) {
    u32 a;
    asm("{ .reg .u64 t; cvta.to.shared.u64 t, %1; cvt.u32.u64 %0, t; }" : "=r"(a) : "l"(p));
    return a;
}
__device__ __forceinline__ void ldsm4(u32 a, u32* r) {
    asm volatile("ldmatrix.sync.aligned.m8n8.x4.shared.b16 {%0,%1,%2,%3}, [%4];"
                 : "=r"(r[0]), "=r"(r[1]), "=r"(r[2]), "=r"(r[3]) : "r"(a));
}
__device__ __forceinline__ void mma1688t(float* c, const u32* a, const u32* b) {
    asm volatile(
        "mma.sync.aligned.m16n8k8.row.col.f32.tf32.tf32.f32 "
        "{%0,%1,%2,%3}, {%4,%5,%6,%7}, {%8,%9}, {%0,%1,%2,%3};"
        : "+f"(c[0]), "+f"(c[1]), "+f"(c[2]), "+f"(c[3])
        : "r"(a[0]), "r"(a[1]), "r"(a[2]), "r"(a[3]), "r"(b[0]), "r"(b[1]));
}
__device__ __forceinline__ float lds32(u32 a) {
    float v; asm volatile("ld.shared.f32 %0, [%1];" : "=f"(v) : "r"(a)); return v;
}
__device__ __forceinline__ u32 rna(float v) {
    u32 o; asm("cvt.rna.tf32.f32 %0, %1;" : "=r"(o) : "f"(v)); return o;
}
__device__ __forceinline__ float rnaf(float v) { return __uint_as_float(rna(v)); }

// ---------------- coefficient path ----------------
__global__ void partial_kernel(const float* __restrict__ eigvs) {
    int b = blockIdx.x >> 5, chunk = blockIdx.x & 31, d = threadIdx.x;
    const float* p = eigvs + ((size_t)b * NN + (size_t)chunk * 128) * DD + d;
    float s = 0.f;
#pragma unroll 8
    for (int r = 0; r < 128; r++) s += p[(size_t)r * DD];
    g_partial[(b * 32 + chunk) * DD + d] = s;
}

__global__ void coeff_kernel(const float* __restrict__ Wa, const float* __restrict__ ba,
                             const float* __restrict__ Wb, const float* __restrict__ bb,
                             const float* __restrict__ Ws, const float* __restrict__ bs) {
    __shared__ float red[15][128];
    int b = blockIdx.x, d = threadIdx.x;
    float s = 0.f;
    for (int c = 0; c < 32; c++) s += g_partial[(b * 32 + c) * DD + d];
    float m = s * (1.0f / NN);
#pragma unroll
    for (int j = 0; j < RHO; j++) {
        red[j][d] = m * Wa[d * RHO + j];
        red[5 + j][d] = m * Wb[d * RHO + j];
        red[10 + j][d] = m * Ws[d * NJ + j];
    }
    __syncthreads();
#pragma unroll
    for (int off = 64; off >= 1; off >>= 1) {
        for (int idx = d; idx < 15 * off; idx += 128) {
            int k = idx / off, e = idx - k * off;
            red[k][e] += red[k][e + off];
        }
        __syncthreads();
    }
    if (d < RHO) {
        g_acoef[b * 8 + d] = red[d][0] + ba[d];
        g_bcoef[b * 8 + d] = red[5 + d][0] + bb[d];
        float sv = red[10 + d][0] + bs[d];
        g_scale[b * 8 + d] = 5.0f / (1.0f + expf(-sv));
    }
}

// fold channel mats through Ww; output Wc^T [d][768] tf32-rounded
__global__ void weight_kernel(const float* __restrict__ WS_, const float* __restrict__ WM,
                              const float* __restrict__ Ww, const float* __restrict__ bS,
                              const float* __restrict__ bM, const float* __restrict__ bw) {
    int blk = blockIdx.x, d = threadIdx.x;
    if (blk < 6 * DD) {
        int s = blk >> 7, i = blk & 127;
        const float* wsrc = (s == 0) ? (WS_ + i * DD) : (WM + (size_t)(s - 1) * DD * DD + i * DD);
        float acc = 0.f;
        for (int e = 0; e < DD; e++) acc += wsrc[e] * Ww[e * DD + d];
        g_WcT[(size_t)d * (6 * DD) + blk] = rnaf(acc);
    } else {
        float acc = bw[d];
        for (int e = 0; e < DD; e++) {
            float cb = bS[e];
            for (int j = 0; j < NJ; j++) cb += bM[j * DD + e];
            acc += cb * Ww[e * DD + d];
        }
        g_cvec[d] = acc;
    }
}

// x -> x^T (tf32-rounded fp32)
__global__ void transpose_x_kernel(const float* __restrict__ x) {
    __shared__ float t[32][33];
    int tx = threadIdx.x, ty = threadIdx.y, b = blockIdx.z;
    int n0 = blockIdx.x * 32, d0 = blockIdx.y * 32;
#pragma unroll
    for (int j = 0; j < 4; j++)
        t[ty + 8 * j][tx] = x[((size_t)b * NN + n0 + ty + 8 * j) * DD + d0 + tx];
    __syncthreads();
#pragma unroll
    for (int j = 0; j < 4; j++)
        g_xT[(size_t)b * DD * NN + (size_t)(d0 + ty + 8 * j) * NN + n0 + tx] =
            rnaf(t[tx][ty + 8 * j]);
}

// fbuild: xt = sum of 2 split-K partials; F output tf32-rounded fp32
__global__ void fbuild_kernel(const float* __restrict__ eigvs) {
    int row0 = blockIdx.x * 16, d = threadIdx.x;
    for (int r = 0; r < 16; r++) {
        int row = row0 + r, b = row >> 12;
        const float* ac = g_acoef + b * 8;
        const float* bc = g_bcoef + b * 8;
        const float* sc = g_scale + b * 8;
        size_t idx = (size_t)row * DD + d;
        float e = eigvs[idx];
        float xv = g_part[idx] + g_part[PARTN + idx];
        float To = 1.f, Te = e, h = bc[0];
#pragma unroll
        for (int i = 1; i < RHO; i++) {
            To = 2.f * e * Te - To;
            Te = 2.f * e * To - Te;
            h += bc[i] * To;
        }
        size_t fb = (size_t)row * (6 * DD);
        g_F32[fb + d] = rnaf(h * xv);
#pragma unroll
        for (int j = 0; j < NJ; j++) {
            float sx = sc[j] * e;
            float To2 = 1.f, Te2 = sx, g = ac[0] * Te2;
#pragma unroll
            for (int i = 1; i < RHO; i++) {
                To2 = 2.f * sx * Te2 - To2;
                Te2 = 2.f * sx * To2 - Te2;
                g += ac[i] * Te2;
            }
            g_F32[fb + (1 + j) * DD + d] = rnaf(g * xv);
        }
    }
}

__global__ void combine2_bias_kernel(const float* __restrict__ bias, float* __restrict__ dst) {
    size_t i = (size_t)blockIdx.x * blockDim.x + threadIdx.x;
    int col = ((int)(i & 31)) * 4;
    const float4* p = (const float4*)g_part;
    const size_t q = PARTN / 4;
    float4 a = p[i], b = p[q + i];
    ((float4*)dst)[i] = make_float4(a.x + b.x + bias[col], a.y + b.y + bias[col + 1],
                                    a.z + b.z + bias[col + 2], a.w + b.w + bias[col + 3]);
}

// ---------------- tf32 GEMM loaders ----------------
// TRANSA A (gemm1): smem [k][m], 64 k-rows x 256B, swizzle ch^((k&7)<<1)
__device__ __forceinline__ void loadA32T(u32 Ab, int k0, const float* A, int lda, int tid) {
#pragma unroll
    for (int i = 0; i < 8; i++) {
        int q = tid + i * 128;
        int row = q >> 4, ch = q & 15;
        const float* g = A + (size_t)(k0 + row) * lda + ch * 4;
        u32 dst = Ab + row * 256 + ((ch ^ ((row & 7) << 1)) << 4);
        asm volatile("cp.async.cg.shared.global [%0], [%1], 16;" :: "r"(dst), "l"(g));
    }
}
// ldsm-layout tile: smem [r][k], NR rows x 256B, swizzle ch^(row&15)
template <int NR>
__device__ __forceinline__ void loadTile32(u32 Tb, int k0, const float* S, int lds, int tid) {
#pragma unroll
    for (int i = 0; i < NR / 8; i++) {
        int q = tid + i * 128;
        int row = q >> 4, ch = q & 15;
        const float* g = S + (size_t)row * lds + k0 + ch * 4;
        u32 dst = Tb + row * 256 + ((ch ^ (row & 15)) << 4);
        asm volatile("cp.async.cg.shared.global [%0], [%1], 16;" :: "r"(dst), "l"(g));
    }
}

// B fragments via ldsm (pre-rounded source): NF/2 ldsm4 -> bf[NF][2]
template <int NF>
__device__ __forceinline__ void ldB32(u32 Bb, int s, int lane, int wn, u32 bf[][2]) {
    int rbase = ((lane >> 4) << 3) + (lane & 7);
    int ch = 2 * s + ((lane >> 3) & 1);
#pragma unroll
    for (int q = 0; q < NF / 2; q++) {
        int row = wn * (NF * 8) + q * 16 + rbase;
        u32 addr = Bb + row * 256 + ((ch ^ (row & 15)) << 4);
        u32 r[4];
        ldsm4(addr, r);
        bf[q * 2][0] = r[0]; bf[q * 2][1] = r[1];
        bf[q * 2 + 1][0] = r[2]; bf[q * 2 + 1][1] = r[3];
    }
}

// A fragments via ldsm; CVTA: apply rna (raw fp32 source) or not (pre-rounded)
template <bool CVTA>
__device__ __forceinline__ void ldA32(u32 Ab2, int s, int lane, int wm, int mt, u32* af) {
    int row = wm * 32 + mt * 16 + ((lane >> 3) & 1) * 8 + (lane & 7);
    int ch = 2 * s + (lane >> 4);
    u32 addr = Ab2 + row * 256 + ((ch ^ (row & 15)) << 4);
    u32 r[4];
    ldsm4(addr, r);
#pragma unroll
    for (int j = 0; j < 4; j++) af[j] = CVTA ? rna(__uint_as_float(r[j])) : r[j];
}

// ---------------- tf32 GEMM: BM=64 x BN, 128 thr, 2 stages ----------------
// warp layout: wm = wid&1 (32-row half), wn = wid>>1 (BN/2-col half); NF = BN/16 frags/warp.
// OUTMODE 0: fp32 split-K partial [m][128]; OUTMODE 1: Z^T rounded transposed
template <bool TRANSA, bool CVTA, int OUTMODE, int NSPLIT, int BN>
__global__ void __launch_bounds__(128, 2)
tf32_gemm(const float* __restrict__ A, const float* __restrict__ B,
          float* __restrict__ Cpart, int K, int lda, int ldb,
          size_t aB, size_t bB) {
    constexpr int NF = BN / 16;
    constexpr u32 STAGE = 16384 + BN * 256;
    extern __shared__ char smem[];
    u32 sb = smem_u32(smem);
    int tid = threadIdx.x, lane = tid & 31, wid = tid >> 5;
    int wm = wid & 1, wn = wid >> 1;
    int bx = blockIdx.x, nh = blockIdx.y;
    int bz = blockIdx.z / NSPLIT, ks = blockIdx.z % NSPLIT;
    const int Klocal = K / NSPLIT;
    const int kofs = ks * Klocal;

    A += bz * aB;
    if (TRANSA) A += (size_t)kofs * lda + (size_t)bx * 64;
    else        A += (size_t)bx * 64 * lda + kofs;
    B += bz * bB + (size_t)nh * BN * ldb + kofs;
    float* C = Cpart + (size_t)ks * PARTN + (size_t)bz * NN * DD;

    float acc[2][NF][4];
#pragma unroll
    for (int a = 0; a < 2; a++)
#pragma unroll
        for (int b = 0; b < NF; b++)
#pragma unroll
            for (int c = 0; c < 4; c++) acc[a][b][c] = 0.f;

    const int NCH = Klocal / KC;
#pragma unroll
    for (int s = 0; s < 2; s++) {
        u32 Ab = sb + s * STAGE;
        if (TRANSA) loadA32T(Ab, s * KC, A, lda, tid);
        else        loadTile32<64>(Ab, s * KC, A, lda, tid);
        loadTile32<BN>(Ab + 16384, s * KC, B, ldb, tid);
        asm volatile("cp.async.commit_group;" ::: "memory");
    }

    const int r = lane >> 2, c = lane & 3;

    // hoisted scalar-A swizzle offsets (TRANSA path)
    u32 aoff[2][4];
    if (TRANSA) {
        int sw0 = c << 1, sw1 = (c + 4) << 1;
#pragma unroll
        for (int mt = 0; mt < 2; mt++) {
            int mb = wm * 32 + mt * 16;
            int mc0 = mb + r, mc1 = mb + r + 8;
            aoff[mt][0] = ((u32)((mc0 >> 2) ^ sw0) << 4) + ((mc0 & 3) << 2);
            aoff[mt][1] = ((u32)((mc1 >> 2) ^ sw0) << 4) + ((mc1 & 3) << 2);
            aoff[mt][2] = 1024u + ((u32)((mc0 >> 2) ^ sw1) << 4) + ((mc0 & 3) << 2);
            aoff[mt][3] = 1024u + ((u32)((mc1 >> 2) ^ sw1) << 4) + ((mc1 & 3) << 2);
        }
    }

    for (int cc = 0; cc < NCH; cc++) {
        int st = cc & 1;
        if (cc + 1 < NCH) asm volatile("cp.async.wait_group 1;" ::: "memory");
        else              asm volatile("cp.async.wait_group 0;" ::: "memory");
        __syncthreads();

        u32 Ab = sb + st * STAGE;
        u32 Bb = Ab + 16384;
#pragma unroll
        for (int s = 0; s < 8; s++) {
            u32 af[2][4], bf2[NF][2];
            if (TRANSA) {
                u32 base = Ab + (u32)(s * 8 + c) * 256;
#pragma unroll
                for (int mt = 0; mt < 2; mt++) {
                    af[mt][0] = rna(lds32(base + aoff[mt][0]));
                    af[mt][1] = rna(lds32(base + aoff[mt][1]));
                    af[mt][2] = rna(lds32(base + aoff[mt][2]));
                    af[mt][3] = rna(lds32(base + aoff[mt][3]));
                }
            } else {
#pragma unroll
                for (int mt = 0; mt < 2; mt++) ldA32<CVTA>(Ab, s, lane, wm, mt, af[mt]);
            }
            ldB32<NF>(Bb, s, lane, wn, bf2);
#pragma unroll
            for (int mt = 0; mt < 2; mt++)
#pragma unroll
                for (int nf = 0; nf < NF; nf++)
                    mma1688t(acc[mt][nf], af[mt], bf2[nf]);
        }
        __syncthreads();
        if (cc + 2 < NCH) {
            u32 Ab2 = sb + st * STAGE;
            if (TRANSA) loadA32T(Ab2, (cc + 2) * KC, A, lda, tid);
            else        loadTile32<64>(Ab2, (cc + 2) * KC, A, lda, tid);
            loadTile32<BN>(Ab2 + 16384, (cc + 2) * KC, B, ldb, tid);
            asm volatile("cp.async.commit_group;" ::: "memory");
        }
    }

    // epilogue
#pragma unroll
    for (int mt = 0; mt < 2; mt++)
#pragma unroll
        for (int nf = 0; nf < NF; nf++) {
            int mloc = bx * 64 + wm * 32 + mt * 16 + r;
            int col = nh * BN + wn * (NF * 8) + nf * 8 + c * 2;
#pragma unroll
            for (int rr = 0; rr < 2; rr++) {
                if (OUTMODE == 0) {
                    size_t off = (size_t)(mloc + rr * 8) * 128 + col;
                    *(float2*)(C + off) = make_float2(acc[mt][nf][rr * 2], acc[mt][nf][rr * 2 + 1]);
                } else {
                    int m = mloc + rr * 8;
                    int b = m >> 12, n = m & 4095;
                    size_t base = (size_t)b * DD * NN + n;
                    g_ZT[base + (size_t)col * NN] = rnaf(acc[mt][nf][rr * 2]);
                    g_ZT[base + (size_t)(col + 1) * NN] = rnaf(acc[mt][nf][rr * 2 + 1]);
                }
            }
        }
}

// ---------------------------------------------------------------
extern "C" void kernel_launch(void* const* d_in, const int* in_sizes, int n_in,
                              void* d_out, int out_size) {
    const float* eigvs = (const float*)d_in[0];
    const float* x = (const float*)d_in[1];
    const float* U = (const float*)d_in[2];
    const float* Wa = (const float*)d_in[3];
    const float* ba = (const float*)d_in[4];
    const float* Wb = (const float*)d_in[5];
    const float* bb = (const float*)d_in[6];
    const float* Ws = (const float*)d_in[7];
    const float* bs = (const float*)d_in[8];
    const float* WS_ = (const float*)d_in[9];
    const float* bS = (const float*)d_in[10];
    const float* WM = (const float*)d_in[11];
    const float* bM = (const float*)d_in[12];
    const float* Ww = (const float*)d_in[13];
    const float* bw = (const float*)d_in[14];
    float* out = (float*)d_out;

    const int SM128 = 2 * (16384 + 128 * 256);   // 98304
    const int SM64 = 2 * (16384 + 64 * 256);     // 65536
    cudaFuncSetAttribute(tf32_gemm<true, true, 0, 2, 128>, cudaFuncAttributeMaxDynamicSharedMemorySize, SM128);
    cudaFuncSetAttribute(tf32_gemm<false, true, 0, 2, 128>, cudaFuncAttributeMaxDynamicSharedMemorySize, SM128);
    cudaFuncSetAttribute(tf32_gemm<false, false, 1, 1, 64>, cudaFuncAttributeMaxDynamicSharedMemorySize, SM64);

    float *pcv, *pp, *pxT, *pZT, *pF, *pW;
    cudaGetSymbolAddress((void**)&pcv, g_cvec);
    cudaGetSymbolAddress((void**)&pp, g_part);
    cudaGetSymbolAddress((void**)&pxT, g_xT);
    cudaGetSymbolAddress((void**)&pZT, g_ZT);
    cudaGetSymbolAddress((void**)&pF, g_F32);
    cudaGetSymbolAddress((void**)&pW, g_WcT);

    const size_t sU = (size_t)NN * NN;
    const size_t sT = (size_t)DD * NN;

    partial_kernel<<<64, 128>>>(eigvs);
    coeff_kernel<<<2, 128>>>(Wa, ba, Wb, bb, Ws, bs);
    weight_kernel<<<769, 128>>>(WS_, WM, Ww, bS, bM, bw);
    transpose_x_kernel<<<dim3(128, 4, 2), dim3(32, 8)>>>(x);

    // gemm1: xt[n][d] = sum_k U[k][n] x[k][d]; BN=128, split-K=2
    tf32_gemm<true, true, 0, 2, 128><<<dim3(64, 1, 4), 128, SM128>>>(
        U, pxT, pp, NN, NN, NN, sU, sT);

    fbuild_kernel<<<512, 128>>>(eigvs);

    // gemm2: Z^T = (F @ Wc)^T; BN=64, K=768, pre-rounded both sides
    tf32_gemm<false, false, 1, 1, 64><<<dim3(128, 2, 1), 128, SM64>>>(
        pF, pW, nullptr, 6 * DD, 6 * DD, 6 * DD, 0, 0);

    // gemm3: out[r][e] = sum_m U[r][m] Z[m][e]; BN=128, split-K=2
    tf32_gemm<false, true, 0, 2, 128><<<dim3(64, 1, 4), 128, SM128>>>(
        U, pZT, pp, NN, NN, NN, sU, sT);

    combine2_bias_kernel<<<1024, 256>>>(pcv, out);
}